// round 2
// baseline (speedup 1.0000x reference)
#include <cuda_runtime.h>
#include <math.h>

// Problem constants
#define B_    2
#define S_    2048
#define H_    4096
#define NH_   32
#define NKV_  2
#define HD_   128
#define ROT_  64
#define QKV_  ((NH_ + 2*NKV_) * HD_)   // 4608
#define MTOK  (B_ * S_)                // 4096

// Scratch (static device globals: no allocation allowed)
__device__ float g_qkv[(size_t)MTOK * QKV_];           // [4096, 4608]  ~75.5 MB
__device__ float g_ctx[(size_t)MTOK * NH_ * HD_];      // [4096, 4096]  ~67 MB
__device__ int   g_posflag;                            // 1 => int32 positions, 0 => int64

// ---------------------------------------------------------------------------
// position dtype detection: int64 little-endian view as int32 gives
// [0,0,1,0,2,0,...]; int32 gives [0,1,2,...]. Positions are arange(S) per batch.
// ---------------------------------------------------------------------------
__global__ void detect_pos_kernel(const int* __restrict__ p32) {
    if (threadIdx.x == 0 && blockIdx.x == 0) {
        g_posflag = (p32[1] == 1 && p32[2] == 2) ? 1 : 0;
    }
}

// ---------------------------------------------------------------------------
// SIMT fp32 GEMM: C[M,N] = A[M,K] @ B[K,N] (+ bias[N]) , all row-major.
// 128x128 block, BK=8, 256 threads, 8x8 per-thread tile, register prefetch.
// M,N,K are multiples of 128 / 8 here.
// ---------------------------------------------------------------------------
__global__ void __launch_bounds__(256) sgemm_kernel(
    const float* __restrict__ A, const float* __restrict__ Bm,
    const float* __restrict__ bias, float* __restrict__ C,
    int M, int N, int K)
{
    __shared__ float As[8][132];   // padded: conflict-free transposed stores
    __shared__ float Bs[8][128];

    const int tid = threadIdx.x;
    const int tx  = tid & 15;
    const int ty  = tid >> 4;
    const int m0  = blockIdx.y << 7;
    const int n0  = blockIdx.x << 7;

    const int arow = tid >> 1;          // 0..127
    const int acol = (tid & 1) << 2;    // 0 or 4
    const int brow = tid >> 5;          // 0..7
    const int bcol = (tid & 31) << 2;   // 0..124

    const float* Aptr = A + (size_t)(m0 + arow) * K + acol;
    const float* Bptr = Bm + (size_t)brow * N + n0 + bcol;

    float acc[8][8];
#pragma unroll
    for (int i = 0; i < 8; ++i)
#pragma unroll
        for (int j = 0; j < 8; ++j) acc[i][j] = 0.f;

    float4 pa = *(const float4*)(Aptr);
    float4 pb = *(const float4*)(Bptr);

    for (int k0 = 0; k0 < K; k0 += 8) {
        As[acol + 0][arow] = pa.x;
        As[acol + 1][arow] = pa.y;
        As[acol + 2][arow] = pa.z;
        As[acol + 3][arow] = pa.w;
        *(float4*)&Bs[brow][bcol] = pb;
        __syncthreads();

        if (k0 + 8 < K) {
            pa = *(const float4*)(Aptr + k0 + 8);
            pb = *(const float4*)(Bptr + (size_t)(k0 + 8) * N);
        }

#pragma unroll
        for (int kk = 0; kk < 8; ++kk) {
            float4 a0 = *(const float4*)&As[kk][ty * 8];
            float4 a1 = *(const float4*)&As[kk][ty * 8 + 4];
            float4 b0 = *(const float4*)&Bs[kk][tx * 8];
            float4 b1 = *(const float4*)&Bs[kk][tx * 8 + 4];
            float ra[8] = {a0.x, a0.y, a0.z, a0.w, a1.x, a1.y, a1.z, a1.w};
            float rb[8] = {b0.x, b0.y, b0.z, b0.w, b1.x, b1.y, b1.z, b1.w};
#pragma unroll
            for (int i = 0; i < 8; ++i)
#pragma unroll
                for (int j = 0; j < 8; ++j)
                    acc[i][j] = fmaf(ra[i], rb[j], acc[i][j]);
        }
        __syncthreads();
    }

    float bv[8];
#pragma unroll
    for (int j = 0; j < 8; ++j)
        bv[j] = bias ? bias[n0 + tx * 8 + j] : 0.f;

#pragma unroll
    for (int i = 0; i < 8; ++i) {
        const int row = m0 + ty * 8 + i;
        float* cp = C + (size_t)row * N + n0 + tx * 8;
        float4 r0, r1;
        r0.x = acc[i][0] + bv[0]; r0.y = acc[i][1] + bv[1];
        r0.z = acc[i][2] + bv[2]; r0.w = acc[i][3] + bv[3];
        r1.x = acc[i][4] + bv[4]; r1.y = acc[i][5] + bv[5];
        r1.z = acc[i][6] + bv[6]; r1.w = acc[i][7] + bv[7];
        *(float4*)cp       = r0;
        *(float4*)(cp + 4) = r1;
    }
}

// ---------------------------------------------------------------------------
// RoPE (GPT-J interleaved) applied in-place to q heads (0..31) and k heads
// (32..33) of g_qkv. First ROT dims only.
// ---------------------------------------------------------------------------
__global__ void rope_kernel(const void* __restrict__ posraw) {
    const int total = MTOK * (NH_ + NKV_) * (ROT_ / 2);
    int idx = blockIdx.x * blockDim.x + threadIdx.x;
    if (idx >= total) return;

    const int i    = idx & 31;                       // rotation pair index 0..31
    const int head = (idx >> 5) % (NH_ + NKV_);      // 0..33
    const int t    = idx / (32 * (NH_ + NKV_));      // token index b*S + s

    long long pos;
    if (g_posflag) pos = ((const int*)posraw)[t];
    else           pos = ((const long long*)posraw)[t];

    // inv_freq computed in double so the fp32 result matches the jax value
    const double e = (double)(2 * i) / 64.0;
    const float inv = (float)(1.0 / pow(10000.0, e));
    const float fr  = (float)pos * inv;
    float sn, cs;
    sincosf(fr, &sn, &cs);

    size_t col;
    if (head < NH_) col = (size_t)head * HD_ + 2 * i;
    else            col = (size_t)NH_ * HD_ + (size_t)(head - NH_) * HD_ + 2 * i;

    float* p = g_qkv + (size_t)t * QKV_ + col;
    const float x1 = p[0];
    const float x2 = p[1];
    p[0] = x1 * cs - x2 * sn;
    p[1] = x2 * cs + x1 * sn;
}

// ---------------------------------------------------------------------------
// Flash attention, causal, GQA (NH=32 q heads share NKV=2 kv heads).
// Grid: (S/64, B*NH). 256 threads: 16x16 layout, 4 q-rows x 4 kv-cols (S phase)
// and 4 q-rows x 8 d-cols (PV phase) per thread.
// Q,K stored transposed [d][row] with pitch 68 => vectorized conflict-free LDS.
// ---------------------------------------------------------------------------
#define QP 68
#define VP 136
#define PP 68
#define ATTN_SMEM ((128 * QP * 2 + 64 * VP + 64 * PP) * (int)sizeof(float))

__global__ void __launch_bounds__(256) attn_kernel() {
    extern __shared__ float sm[];
    float* Qt = sm;                 // [128][QP]
    float* Kt = Qt + 128 * QP;      // [128][QP]
    float* Vs = Kt + 128 * QP;      // [64][VP]
    float* Ps = Vs + 64 * VP;       // [64][PP]

    const int tid = threadIdx.x;
    const int tx  = tid & 15;
    const int ty  = tid >> 4;
    const int qt  = blockIdx.x;
    const int bh  = blockIdx.y;
    const int b   = bh >> 5;        // / NH_
    const int h   = bh & 31;
    const int kh  = h >> 4;         // / (NH_/NKV_)
    const int q0  = qt * 64;
    const float scale = 0.08838834764831845f;   // HD^-0.5

    // Load Q tile transposed, pre-scaled
#pragma unroll
    for (int it = 0; it < 8; ++it) {
        const int idx = tid + it * 256;        // 0..2047
        const int r   = idx >> 5;              // 0..63
        const int c4  = (idx & 31) << 2;       // 0,4,..,124
        const float4 v = *(const float4*)(g_qkv +
            (size_t)(b * S_ + q0 + r) * QKV_ + (size_t)h * HD_ + c4);
        Qt[(c4 + 0) * QP + r] = v.x * scale;
        Qt[(c4 + 1) * QP + r] = v.y * scale;
        Qt[(c4 + 2) * QP + r] = v.z * scale;
        Qt[(c4 + 3) * QP + r] = v.w * scale;
    }

    float m_i[4], l_i[4], o[4][8];
#pragma unroll
    for (int i = 0; i < 4; ++i) {
        m_i[i] = -INFINITY;
        l_i[i] = 0.f;
#pragma unroll
        for (int c = 0; c < 8; ++c) o[i][c] = 0.f;
    }

    for (int kt = 0; kt <= qt; ++kt) {
        const int k0 = kt * 64;
        __syncthreads();   // protect Kt/Vs/Ps from previous iteration readers

        // Load K (transposed) and V tiles
#pragma unroll
        for (int it = 0; it < 8; ++it) {
            const int idx = tid + it * 256;
            const int r   = idx >> 5;
            const int c4  = (idx & 31) << 2;
            const size_t rowbase = (size_t)(b * S_ + k0 + r) * QKV_;
            const float4 kv4 = *(const float4*)(g_qkv + rowbase +
                (size_t)NH_ * HD_ + (size_t)kh * HD_ + c4);
            Kt[(c4 + 0) * QP + r] = kv4.x;
            Kt[(c4 + 1) * QP + r] = kv4.y;
            Kt[(c4 + 2) * QP + r] = kv4.z;
            Kt[(c4 + 3) * QP + r] = kv4.w;
            const float4 vv4 = *(const float4*)(g_qkv + rowbase +
                (size_t)(NH_ + NKV_) * HD_ + (size_t)kh * HD_ + c4);
            *(float4*)&Vs[r * VP + c4] = vv4;
        }
        __syncthreads();

        // S = (Q*scale) @ K^T   (4x4 per thread)
        float s[4][4];
#pragma unroll
        for (int i = 0; i < 4; ++i)
#pragma unroll
            for (int j = 0; j < 4; ++j) s[i][j] = 0.f;

#pragma unroll 8
        for (int k = 0; k < 128; ++k) {
            const float4 qa = *(const float4*)&Qt[k * QP + ty * 4];
            const float4 kb = *(const float4*)&Kt[k * QP + tx * 4];
            const float ra[4] = {qa.x, qa.y, qa.z, qa.w};
            const float rb[4] = {kb.x, kb.y, kb.z, kb.w};
#pragma unroll
            for (int i = 0; i < 4; ++i)
#pragma unroll
                for (int j = 0; j < 4; ++j)
                    s[i][j] = fmaf(ra[i], rb[j], s[i][j]);
        }

        // Causal mask (only needed on the diagonal tile)
        if (kt == qt) {
#pragma unroll
            for (int i = 0; i < 4; ++i)
#pragma unroll
                for (int j = 0; j < 4; ++j)
                    if (k0 + tx * 4 + j > q0 + ty * 4 + i) s[i][j] = -INFINITY;
        }

        // Online softmax update per row; write P tile to smem
#pragma unroll
        for (int i = 0; i < 4; ++i) {
            float tm = fmaxf(fmaxf(s[i][0], s[i][1]), fmaxf(s[i][2], s[i][3]));
#pragma unroll
            for (int off = 8; off > 0; off >>= 1)
                tm = fmaxf(tm, __shfl_xor_sync(0xffffffffu, tm, off));

            const float mnew  = fmaxf(m_i[i], tm);
            const float alpha = __expf(m_i[i] - mnew);

            float p0 = __expf(s[i][0] - mnew);
            float p1 = __expf(s[i][1] - mnew);
            float p2 = __expf(s[i][2] - mnew);
            float p3 = __expf(s[i][3] - mnew);
            float rs = p0 + p1 + p2 + p3;
#pragma unroll
            for (int off = 8; off > 0; off >>= 1)
                rs += __shfl_xor_sync(0xffffffffu, rs, off);

            l_i[i] = l_i[i] * alpha + rs;
            m_i[i] = mnew;
#pragma unroll
            for (int c = 0; c < 8; ++c) o[i][c] *= alpha;

            float4 pv; pv.x = p0; pv.y = p1; pv.z = p2; pv.w = p3;
            *(float4*)&Ps[(ty * 4 + i) * PP + tx * 4] = pv;
        }
        __syncthreads();

        // O += P @ V   (4 rows x 8 d-cols per thread)
#pragma unroll 4
        for (int j = 0; j < 64; ++j) {
            const float4 v0 = *(const float4*)&Vs[j * VP + tx * 8];
            const float4 v1 = *(const float4*)&Vs[j * VP + tx * 8 + 4];
#pragma unroll
            for (int i = 0; i < 4; ++i) {
                const float pr = Ps[(ty * 4 + i) * PP + j];
                o[i][0] = fmaf(pr, v0.x, o[i][0]);
                o[i][1] = fmaf(pr, v0.y, o[i][1]);
                o[i][2] = fmaf(pr, v0.z, o[i][2]);
                o[i][3] = fmaf(pr, v0.w, o[i][3]);
                o[i][4] = fmaf(pr, v1.x, o[i][4]);
                o[i][5] = fmaf(pr, v1.y, o[i][5]);
                o[i][6] = fmaf(pr, v1.z, o[i][6]);
                o[i][7] = fmaf(pr, v1.w, o[i][7]);
            }
        }
    }

    // Normalize and store context: layout [B,S,NH,HD]
#pragma unroll
    for (int i = 0; i < 4; ++i) {
        const float inv = 1.f / l_i[i];
        const int qrow  = q0 + ty * 4 + i;
        float4 r0, r1;
        r0.x = o[i][0] * inv; r0.y = o[i][1] * inv;
        r0.z = o[i][2] * inv; r0.w = o[i][3] * inv;
        r1.x = o[i][4] * inv; r1.y = o[i][5] * inv;
        r1.z = o[i][6] * inv; r1.w = o[i][7] * inv;
        const size_t base = ((size_t)(b * S_ + qrow) * NH_ + h) * HD_ + tx * 8;
        *(float4*)&g_ctx[base]     = r0;
        *(float4*)&g_ctx[base + 4] = r1;
    }
}

// ---------------------------------------------------------------------------
// Launch: QKV GEMM -> pos detect -> RoPE -> attention -> output GEMM
// ---------------------------------------------------------------------------
extern "C" void kernel_launch(void* const* d_in, const int* in_sizes, int n_in,
                              void* d_out, int out_size)
{
    const float* hs   = (const float*)d_in[0];
    const void*  pos  = d_in[1];
    const float* Wqkv = (const float*)d_in[2];
    const float* bqkv = (const float*)d_in[3];
    const float* Wo   = (const float*)d_in[4];
    float*       out  = (float*)d_out;

    float* qkv = nullptr;
    float* ctx = nullptr;
    cudaGetSymbolAddress((void**)&qkv, g_qkv);
    cudaGetSymbolAddress((void**)&ctx, g_ctx);

    cudaFuncSetAttribute(attn_kernel,
                         cudaFuncAttributeMaxDynamicSharedMemorySize, ATTN_SMEM);

    // 1) QKV projection: [4096,4096] @ [4096,4608] + bias
    sgemm_kernel<<<dim3(QKV_ / 128, MTOK / 128), 256>>>(
        hs, Wqkv, bqkv, qkv, MTOK, QKV_, H_);

    // 2) position dtype detection + RoPE in-place
    detect_pos_kernel<<<1, 32>>>((const int*)pos);
    {
        const int total = MTOK * (NH_ + NKV_) * (ROT_ / 2);
        rope_kernel<<<(total + 255) / 256, 256>>>(pos);
    }

    // 3) causal GQA flash attention -> g_ctx
    attn_kernel<<<dim3(S_ / 64, B_ * NH_), 256, ATTN_SMEM>>>();

    // 4) output projection: [4096,4096] @ [4096,4096]
    sgemm_kernel<<<dim3(H_ / 128, MTOK / 128), 256>>>(
        ctx, Wo, nullptr, out, MTOK, H_, H_);
}

// round 8
// speedup vs baseline: 1.8163x; 1.8163x over previous
#include <cuda_runtime.h>
#include <math.h>
#include <stdint.h>

// Problem constants
#define B_    2
#define S_    2048
#define H_    4096
#define NH_   32
#define NKV_  2
#define HD_   128
#define ROT_  64
#define QKV_  ((NH_ + 2*NKV_) * HD_)   // 4608
#define MTOK  (B_ * S_)                // 4096

// Scratch (static device globals: no allocation allowed)
__device__ float g_qkv[(size_t)MTOK * QKV_];        // [4096,4608]
__device__ float g_ctx[(size_t)MTOK * NH_ * HD_];   // [4096,4096]
__device__ int   g_posflag;

// ===========================================================================
// helpers
// ===========================================================================
#define CP_ASYNC16(dst_smem, src_gmem) \
    asm volatile("cp.async.cg.shared.global [%0], [%1], 16;" \
                 :: "r"(dst_smem), "l"(src_gmem) : "memory")
#define CP_COMMIT() asm volatile("cp.async.commit_group;" ::: "memory")
#define CP_WAIT(n)  asm volatile("cp.async.wait_group %0;" :: "n"(n) : "memory")

__device__ __forceinline__ uint32_t smem_to_u32(const void* p) {
    uint32_t a;
    asm("{ .reg .u64 t; cvta.to.shared.u64 t, %1; cvt.u32.u64 %0, t; }"
        : "=r"(a) : "l"(p));
    return a;
}
__device__ __forceinline__ uint32_t cvt_rna(float x) {
    uint32_t r;
    asm("cvt.rna.tf32.f32 %0, %1;" : "=r"(r) : "f"(x));
    return r;
}
__device__ __forceinline__ void mma_tf32(float* c, const uint32_t* a, const uint32_t* b) {
    asm volatile(
        "mma.sync.aligned.m16n8k8.row.col.f32.tf32.tf32.f32 "
        "{%0,%1,%2,%3}, {%4,%5,%6,%7}, {%8,%9}, {%0,%1,%2,%3};"
        : "+f"(c[0]), "+f"(c[1]), "+f"(c[2]), "+f"(c[3])
        : "r"(a[0]), "r"(a[1]), "r"(a[2]), "r"(a[3]), "r"(b[0]), "r"(b[1]));
}

// ===========================================================================
// tf32 mma.sync GEMM: C[M,N] = A[M,K] @ B[K,N] (+ bias[N]), all row-major fp32.
// CTA tile 128x128, BK=32, 256 threads (8 warps, 2x4), warp tile 64x32.
// A smem [128][36] (pad 36: bank-conflict-free frag loads), B smem [32][132].
// Double-buffered cp.async; operands rna-rounded to tf32 in register.
// M,N,K multiples of 128/128/32.
// ===========================================================================
#define APITCH 36
#define BPITCH 132
#define ASTAGE (128 * APITCH * 4)              // 18432 B
#define BSTAGE (32 * BPITCH * 4)               // 16896 B
#define STAGE_BYTES (ASTAGE + BSTAGE)          // 35328 B
#define GEMM_DSMEM (2 * STAGE_BYTES)           // 70656 B

__global__ void __launch_bounds__(256, 2) gemm_tf32_kernel(
    const float* __restrict__ A, const float* __restrict__ Bm,
    const float* __restrict__ bias, float* __restrict__ C,
    int M, int N, int K, int mTiles, int nTiles, int group)
{
    extern __shared__ float dsm[];

    const int tid  = threadIdx.x;
    const int wid  = tid >> 5;
    const int lane = tid & 31;
    const int g    = lane >> 2;   // group id 0..7
    const int tig  = lane & 3;    // thread-in-group 0..3
    const int wm   = wid & 1;     // warp m index (0..1) -> 64 rows
    const int wn   = wid >> 1;    // warp n index (0..3) -> 32 cols

    // tile swizzle for L2 reuse
    const int bid = blockIdx.x;
    const int tpg = group * nTiles;
    const int gi  = bid / tpg;
    const int rr  = bid % tpg;
    const int rem = mTiles - gi * group;
    const int gm  = rem < group ? rem : group;
    const int tm  = gi * group + rr % gm;
    const int tn  = rr / gm;
    const int m0  = tm * 128;
    const int n0  = tn * 128;

    const uint32_t base_u = smem_to_u32(dsm);

    // ---- stage loader ----
    auto load_stage = [&](int s, int kc) {
        const uint32_t sA = base_u + s * STAGE_BYTES;
        const uint32_t sB = sA + ASTAGE;
        const float* Ab = A + (size_t)m0 * K + kc * 32;
        const float* Bb = Bm + (size_t)(kc * 32) * N + n0;
#pragma unroll
        for (int i = 0; i < 4; ++i) {          // A: 128 rows x 8 granules
            const int id  = tid + i * 256;
            const int row = id >> 3;
            const int gg  = id & 7;
            CP_ASYNC16(sA + row * (APITCH * 4) + gg * 16,
                       Ab + (size_t)row * K + gg * 4);
        }
#pragma unroll
        for (int i = 0; i < 4; ++i) {          // B: 32 rows x 32 granules
            const int id  = tid + i * 256;
            const int row = id >> 5;
            const int gg  = id & 31;
            CP_ASYNC16(sB + row * (BPITCH * 4) + gg * 16,
                       Bb + (size_t)row * N + gg * 4);
        }
    };

    float acc[4][4][4];
#pragma unroll
    for (int mt = 0; mt < 4; ++mt)
#pragma unroll
        for (int nt = 0; nt < 4; ++nt)
#pragma unroll
            for (int r = 0; r < 4; ++r) acc[mt][nt][r] = 0.f;

    const int NK = K / 32;
    load_stage(0, 0);
    CP_COMMIT();

    for (int kc = 0; kc < NK; ++kc) {
        const int s = kc & 1;
        if (kc + 1 < NK) { load_stage(s ^ 1, kc + 1); CP_COMMIT(); }

        if (kc + 1 < NK) { CP_WAIT(1); } else { CP_WAIT(0); }
        __syncthreads();

        const float* As = dsm + (size_t)s * (STAGE_BYTES / 4);
        const float* Bs = As + ASTAGE / 4;

#pragma unroll
        for (int ks = 0; ks < 4; ++ks) {
            // batch all fragment loads first (clean LDS -> CVT -> HMMA pipeline)
            float araw[4][4];
#pragma unroll
            for (int mt = 0; mt < 4; ++mt) {
                const int r0 = wm * 64 + mt * 16 + g;
                const int c0 = ks * 8 + tig;
                araw[mt][0] = As[(r0    ) * APITCH + c0    ];
                araw[mt][1] = As[(r0 + 8) * APITCH + c0    ];
                araw[mt][2] = As[(r0    ) * APITCH + c0 + 4];
                araw[mt][3] = As[(r0 + 8) * APITCH + c0 + 4];
            }
            float braw[4][2];
#pragma unroll
            for (int nt = 0; nt < 4; ++nt) {
                const int cn = wn * 32 + nt * 8 + g;
                braw[nt][0] = Bs[(ks * 8 + tig    ) * BPITCH + cn];
                braw[nt][1] = Bs[(ks * 8 + tig + 4) * BPITCH + cn];
            }

            uint32_t af[4][4];
#pragma unroll
            for (int mt = 0; mt < 4; ++mt)
#pragma unroll
                for (int r = 0; r < 4; ++r) af[mt][r] = cvt_rna(araw[mt][r]);
            uint32_t bf[4][2];
#pragma unroll
            for (int nt = 0; nt < 4; ++nt) {
                bf[nt][0] = cvt_rna(braw[nt][0]);
                bf[nt][1] = cvt_rna(braw[nt][1]);
            }

#pragma unroll
            for (int mt = 0; mt < 4; ++mt)
#pragma unroll
                for (int nt = 0; nt < 4; ++nt)
                    mma_tf32(acc[mt][nt], af[mt], bf[nt]);
        }
        __syncthreads();
    }

    // ---- epilogue: write C (+bias) ----
#pragma unroll
    for (int mt = 0; mt < 4; ++mt) {
        const int row = m0 + wm * 64 + mt * 16 + g;
#pragma unroll
        for (int nt = 0; nt < 4; ++nt) {
            const int col = n0 + wn * 32 + nt * 8 + tig * 2;
            float b0 = 0.f, b1 = 0.f;
            if (bias) { b0 = bias[col]; b1 = bias[col + 1]; }
            float2 v0, v1;
            v0.x = acc[mt][nt][0] + b0; v0.y = acc[mt][nt][1] + b1;
            v1.x = acc[mt][nt][2] + b0; v1.y = acc[mt][nt][3] + b1;
            *(float2*)&C[(size_t)row * N + col]       = v0;
            *(float2*)&C[(size_t)(row + 8) * N + col] = v1;
        }
    }
}

// ===========================================================================
// position dtype detection
// ===========================================================================
__global__ void detect_pos_kernel(const int* __restrict__ p32) {
    if (threadIdx.x == 0 && blockIdx.x == 0)
        g_posflag = (p32[1] == 1 && p32[2] == 2) ? 1 : 0;
}

// ===========================================================================
// RoPE (GPT-J interleaved), in-place on q heads 0..31 and k heads 32..33
// ===========================================================================
__global__ void rope_kernel(const void* __restrict__ posraw) {
    const int total = MTOK * (NH_ + NKV_) * (ROT_ / 2);
    int idx = blockIdx.x * blockDim.x + threadIdx.x;
    if (idx >= total) return;

    const int i    = idx & 31;
    const int head = (idx >> 5) % (NH_ + NKV_);
    const int t    = idx / (32 * (NH_ + NKV_));

    long long pos;
    if (g_posflag) pos = ((const int*)posraw)[t];
    else           pos = ((const long long*)posraw)[t];

    const double e  = (double)(2 * i) / 64.0;
    const float inv = (float)(1.0 / pow(10000.0, e));
    const float fr  = (float)pos * inv;
    float sn, cs;
    sincosf(fr, &sn, &cs);

    size_t col;
    if (head < NH_) col = (size_t)head * HD_ + 2 * i;
    else            col = (size_t)NH_ * HD_ + (size_t)(head - NH_) * HD_ + 2 * i;

    float* p = g_qkv + (size_t)t * QKV_ + col;
    const float x1 = p[0];
    const float x2 = p[1];
    p[0] = x1 * cs - x2 * sn;
    p[1] = x2 * cs + x1 * sn;
}

// ===========================================================================
// Flash attention (fp32 SIMT), causal, GQA.
// ===========================================================================
#define QP 68
#define VP 136
#define PP 68
#define ATTN_SMEM ((128 * QP * 2 + 64 * VP + 64 * PP) * (int)sizeof(float))

__global__ void __launch_bounds__(256) attn_kernel() {
    extern __shared__ float sm[];
    float* Qt = sm;
    float* Kt = Qt + 128 * QP;
    float* Vs = Kt + 128 * QP;
    float* Ps = Vs + 64 * VP;

    const int tid = threadIdx.x;
    const int tx  = tid & 15;
    const int ty  = tid >> 4;
    const int qt  = blockIdx.x;
    const int bh  = blockIdx.y;
    const int b   = bh >> 5;
    const int h   = bh & 31;
    const int kh  = h >> 4;
    const int q0  = qt * 64;
    const float scale = 0.08838834764831845f;

#pragma unroll
    for (int it = 0; it < 8; ++it) {
        const int idx = tid + it * 256;
        const int r   = idx >> 5;
        const int c4  = (idx & 31) << 2;
        const float4 v = *(const float4*)(g_qkv +
            (size_t)(b * S_ + q0 + r) * QKV_ + (size_t)h * HD_ + c4);
        Qt[(c4 + 0) * QP + r] = v.x * scale;
        Qt[(c4 + 1) * QP + r] = v.y * scale;
        Qt[(c4 + 2) * QP + r] = v.z * scale;
        Qt[(c4 + 3) * QP + r] = v.w * scale;
    }

    float m_i[4], l_i[4], o[4][8];
#pragma unroll
    for (int i = 0; i < 4; ++i) {
        m_i[i] = -INFINITY;
        l_i[i] = 0.f;
#pragma unroll
        for (int c = 0; c < 8; ++c) o[i][c] = 0.f;
    }

    for (int kt = 0; kt <= qt; ++kt) {
        const int k0 = kt * 64;
        __syncthreads();

#pragma unroll
        for (int it = 0; it < 8; ++it) {
            const int idx = tid + it * 256;
            const int r   = idx >> 5;
            const int c4  = (idx & 31) << 2;
            const size_t rowbase = (size_t)(b * S_ + k0 + r) * QKV_;
            const float4 kv4 = *(const float4*)(g_qkv + rowbase +
                (size_t)NH_ * HD_ + (size_t)kh * HD_ + c4);
            Kt[(c4 + 0) * QP + r] = kv4.x;
            Kt[(c4 + 1) * QP + r] = kv4.y;
            Kt[(c4 + 2) * QP + r] = kv4.z;
            Kt[(c4 + 3) * QP + r] = kv4.w;
            const float4 vv4 = *(const float4*)(g_qkv + rowbase +
                (size_t)(NH_ + NKV_) * HD_ + (size_t)kh * HD_ + c4);
            *(float4*)&Vs[r * VP + c4] = vv4;
        }
        __syncthreads();

        float s[4][4];
#pragma unroll
        for (int i = 0; i < 4; ++i)
#pragma unroll
            for (int j = 0; j < 4; ++j) s[i][j] = 0.f;

#pragma unroll 8
        for (int k = 0; k < 128; ++k) {
            const float4 qa = *(const float4*)&Qt[k * QP + ty * 4];
            const float4 kb = *(const float4*)&Kt[k * QP + tx * 4];
            const float ra[4] = {qa.x, qa.y, qa.z, qa.w};
            const float rb[4] = {kb.x, kb.y, kb.z, kb.w};
#pragma unroll
            for (int i = 0; i < 4; ++i)
#pragma unroll
                for (int j = 0; j < 4; ++j)
                    s[i][j] = fmaf(ra[i], rb[j], s[i][j]);
        }

        if (kt == qt) {
#pragma unroll
            for (int i = 0; i < 4; ++i)
#pragma unroll
                for (int j = 0; j < 4; ++j)
                    if (k0 + tx * 4 + j > q0 + ty * 4 + i) s[i][j] = -INFINITY;
        }

#pragma unroll
        for (int i = 0; i < 4; ++i) {
            float tm = fmaxf(fmaxf(s[i][0], s[i][1]), fmaxf(s[i][2], s[i][3]));
#pragma unroll
            for (int off = 8; off > 0; off >>= 1)
                tm = fmaxf(tm, __shfl_xor_sync(0xffffffffu, tm, off));

            const float mnew  = fmaxf(m_i[i], tm);
            const float alpha = __expf(m_i[i] - mnew);

            float p0 = __expf(s[i][0] - mnew);
            float p1 = __expf(s[i][1] - mnew);
            float p2 = __expf(s[i][2] - mnew);
            float p3 = __expf(s[i][3] - mnew);
            float rs = p0 + p1 + p2 + p3;
#pragma unroll
            for (int off = 8; off > 0; off >>= 1)
                rs += __shfl_xor_sync(0xffffffffu, rs, off);

            l_i[i] = l_i[i] * alpha + rs;
            m_i[i] = mnew;
#pragma unroll
            for (int c = 0; c < 8; ++c) o[i][c] *= alpha;

            float4 pv; pv.x = p0; pv.y = p1; pv.z = p2; pv.w = p3;
            *(float4*)&Ps[(ty * 4 + i) * PP + tx * 4] = pv;
        }
        __syncthreads();

#pragma unroll 4
        for (int j = 0; j < 64; ++j) {
            const float4 v0 = *(const float4*)&Vs[j * VP + tx * 8];
            const float4 v1 = *(const float4*)&Vs[j * VP + tx * 8 + 4];
#pragma unroll
            for (int i = 0; i < 4; ++i) {
                const float pr = Ps[(ty * 4 + i) * PP + j];
                o[i][0] = fmaf(pr, v0.x, o[i][0]);
                o[i][1] = fmaf(pr, v0.y, o[i][1]);
                o[i][2] = fmaf(pr, v0.z, o[i][2]);
                o[i][3] = fmaf(pr, v0.w, o[i][3]);
                o[i][4] = fmaf(pr, v1.x, o[i][4]);
                o[i][5] = fmaf(pr, v1.y, o[i][5]);
                o[i][6] = fmaf(pr, v1.z, o[i][6]);
                o[i][7] = fmaf(pr, v1.w, o[i][7]);
            }
        }
    }

#pragma unroll
    for (int i = 0; i < 4; ++i) {
        const float inv = 1.f / l_i[i];
        const int qrow  = q0 + ty * 4 + i;
        float4 r0, r1;
        r0.x = o[i][0] * inv; r0.y = o[i][1] * inv;
        r0.z = o[i][2] * inv; r0.w = o[i][3] * inv;
        r1.x = o[i][4] * inv; r1.y = o[i][5] * inv;
        r1.z = o[i][6] * inv; r1.w = o[i][7] * inv;
        const size_t base = ((size_t)(b * S_ + qrow) * NH_ + h) * HD_ + tx * 8;
        *(float4*)&g_ctx[base]     = r0;
        *(float4*)&g_ctx[base + 4] = r1;
    }
}

// ===========================================================================
// Launch
// ===========================================================================
extern "C" void kernel_launch(void* const* d_in, const int* in_sizes, int n_in,
                              void* d_out, int out_size)
{
    const float* hs   = (const float*)d_in[0];
    const void*  pos  = d_in[1];
    const float* Wqkv = (const float*)d_in[2];
    const float* bqkv = (const float*)d_in[3];
    const float* Wo   = (const float*)d_in[4];
    float*       out  = (float*)d_out;

    float *qkv, *ctx;
    cudaGetSymbolAddress((void**)&qkv, g_qkv);
    cudaGetSymbolAddress((void**)&ctx, g_ctx);

    cudaFuncSetAttribute(attn_kernel,
                         cudaFuncAttributeMaxDynamicSharedMemorySize, ATTN_SMEM);
    cudaFuncSetAttribute(gemm_tf32_kernel,
                         cudaFuncAttributeMaxDynamicSharedMemorySize, GEMM_DSMEM);

    // 1) QKV projection: [4096,4096] @ [4096,4608] + bias  (tf32 mma.sync)
    gemm_tf32_kernel<<<(MTOK / 128) * (QKV_ / 128), 256, GEMM_DSMEM>>>(
        hs, Wqkv, bqkv, qkv, MTOK, QKV_, H_, MTOK / 128, QKV_ / 128, 8);

    // 2) position dtype detect + RoPE in-place
    detect_pos_kernel<<<1, 32>>>((const int*)pos);
    {
        const int total = MTOK * (NH_ + NKV_) * (ROT_ / 2);
        rope_kernel<<<(total + 255) / 256, 256>>>(pos);
    }

    // 3) causal GQA flash attention -> g_ctx
    attn_kernel<<<dim3(S_ / 64, B_ * NH_), 256, ATTN_SMEM>>>();

    // 4) output projection: [4096,4096] @ [4096,4096]  (tf32 mma.sync)
    gemm_tf32_kernel<<<(MTOK / 128) * (H_ / 128), 256, GEMM_DSMEM>>>(
        ctx, Wo, nullptr, out, MTOK, H_, H_, MTOK / 128, H_ / 128, 8);
}

// round 9
// speedup vs baseline: 2.4799x; 1.3653x over previous
#include <cuda_runtime.h>
#include <math.h>
#include <stdint.h>

// Problem constants
#define B_    2
#define S_    2048
#define H_    4096
#define NH_   32
#define NKV_  2
#define HD_   128
#define ROT_  64
#define QKV_  ((NH_ + 2*NKV_) * HD_)   // 4608
#define MTOK  (B_ * S_)                // 4096

// Scratch (static device globals: no allocation allowed)
__device__ float g_qkv[(size_t)MTOK * QKV_];        // [4096,4608] fp32
__device__ float g_ctx[(size_t)MTOK * NH_ * HD_];   // [4096,4096] tf32-rounded
__device__ float g_hsr[(size_t)MTOK * H_];          // hs rounded to tf32
__device__ float g_wqr[(size_t)H_ * QKV_];          // Wqkv rounded
__device__ float g_wor[(size_t)H_ * H_];            // Wo rounded
__device__ int   g_posflag;

// ===========================================================================
// helpers
// ===========================================================================
#define CP_ASYNC16(dst_smem, src_gmem) \
    asm volatile("cp.async.cg.shared.global [%0], [%1], 16;" \
                 :: "r"(dst_smem), "l"(src_gmem) : "memory")
#define CP_COMMIT() asm volatile("cp.async.commit_group;" ::: "memory")
#define CP_WAIT(n)  asm volatile("cp.async.wait_group %0;" :: "n"(n) : "memory")

__device__ __forceinline__ uint32_t smem_to_u32(const void* p) {
    uint32_t a;
    asm("{ .reg .u64 t; cvta.to.shared.u64 t, %1; cvt.u32.u64 %0, t; }"
        : "=r"(a) : "l"(p));
    return a;
}
__device__ __forceinline__ uint32_t cvt_rna(float x) {
    uint32_t r;
    asm("cvt.rna.tf32.f32 %0, %1;" : "=r"(r) : "f"(x));
    return r;
}
__device__ __forceinline__ float rna_f(float x) {
    return __uint_as_float(cvt_rna(x));
}
__device__ __forceinline__ void mma_tf32(float* c, const uint32_t* a, const uint32_t* b) {
    asm volatile(
        "mma.sync.aligned.m16n8k8.row.col.f32.tf32.tf32.f32 "
        "{%0,%1,%2,%3}, {%4,%5,%6,%7}, {%8,%9}, {%0,%1,%2,%3};"
        : "+f"(c[0]), "+f"(c[1]), "+f"(c[2]), "+f"(c[3])
        : "r"(a[0]), "r"(a[1]), "r"(a[2]), "r"(a[3]), "r"(b[0]), "r"(b[1]));
}

// ===========================================================================
// pre-round pass: out[i] = tf32_rna(in[i])
// ===========================================================================
__global__ void round_copy_kernel(const float* __restrict__ in,
                                  float* __restrict__ out, int n4) {
    int i = blockIdx.x * blockDim.x + threadIdx.x;
    if (i >= n4) return;
    float4 v = ((const float4*)in)[i];
    v.x = rna_f(v.x); v.y = rna_f(v.y);
    v.z = rna_f(v.z); v.w = rna_f(v.w);
    ((float4*)out)[i] = v;
}

// ===========================================================================
// tf32 mma.sync GEMM: C[M,N] = A[M,K] @ B[K,N] (+ bias[N]), row-major fp32.
// A and B are PRE-ROUNDED to tf32 values -> no CVT in mainloop (raw bits).
// CTA tile 128x128, BK=32, 256 threads (8 warps 2x4), warp tile 64x32.
// ===========================================================================
#define APITCH 36
#define BPITCH 132
#define ASTAGE (128 * APITCH * 4)
#define BSTAGE (32 * BPITCH * 4)
#define STAGE_BYTES (ASTAGE + BSTAGE)
#define GEMM_DSMEM (2 * STAGE_BYTES)

__global__ void __launch_bounds__(256, 2) gemm_tf32_kernel(
    const float* __restrict__ A, const float* __restrict__ Bm,
    const float* __restrict__ bias, float* __restrict__ C,
    int M, int N, int K, int mTiles, int nTiles, int group)
{
    extern __shared__ float dsm[];

    const int tid  = threadIdx.x;
    const int wid  = tid >> 5;
    const int lane = tid & 31;
    const int g    = lane >> 2;
    const int tig  = lane & 3;
    const int wm   = wid & 1;
    const int wn   = wid >> 1;

    const int bid = blockIdx.x;
    const int tpg = group * nTiles;
    const int gi  = bid / tpg;
    const int rr  = bid % tpg;
    const int rem = mTiles - gi * group;
    const int gm  = rem < group ? rem : group;
    const int tm  = gi * group + rr % gm;
    const int tn  = rr / gm;
    const int m0  = tm * 128;
    const int n0  = tn * 128;

    const uint32_t base_u = smem_to_u32(dsm);

    auto load_stage = [&](int s, int kc) {
        const uint32_t sA = base_u + s * STAGE_BYTES;
        const uint32_t sB = sA + ASTAGE;
        const float* Ab = A + (size_t)m0 * K + kc * 32;
        const float* Bb = Bm + (size_t)(kc * 32) * N + n0;
#pragma unroll
        for (int i = 0; i < 4; ++i) {
            const int id  = tid + i * 256;
            const int row = id >> 3;
            const int gg  = id & 7;
            CP_ASYNC16(sA + row * (APITCH * 4) + gg * 16,
                       Ab + (size_t)row * K + gg * 4);
        }
#pragma unroll
        for (int i = 0; i < 4; ++i) {
            const int id  = tid + i * 256;
            const int row = id >> 5;
            const int gg  = id & 31;
            CP_ASYNC16(sB + row * (BPITCH * 4) + gg * 16,
                       Bb + (size_t)row * N + gg * 4);
        }
    };

    float acc[4][4][4];
#pragma unroll
    for (int mt = 0; mt < 4; ++mt)
#pragma unroll
        for (int nt = 0; nt < 4; ++nt)
#pragma unroll
            for (int r = 0; r < 4; ++r) acc[mt][nt][r] = 0.f;

    const int NK = K / 32;
    load_stage(0, 0);
    CP_COMMIT();

    for (int kc = 0; kc < NK; ++kc) {
        const int s = kc & 1;
        if (kc + 1 < NK) { load_stage(s ^ 1, kc + 1); CP_COMMIT(); }
        if (kc + 1 < NK) { CP_WAIT(1); } else { CP_WAIT(0); }
        __syncthreads();

        const float* As = dsm + (size_t)s * (STAGE_BYTES / 4);
        const float* Bs = As + ASTAGE / 4;

#pragma unroll
        for (int ks = 0; ks < 4; ++ks) {
            uint32_t af[4][4];
#pragma unroll
            for (int mt = 0; mt < 4; ++mt) {
                const int r0 = wm * 64 + mt * 16 + g;
                const int c0 = ks * 8 + tig;
                af[mt][0] = __float_as_uint(As[(r0    ) * APITCH + c0    ]);
                af[mt][1] = __float_as_uint(As[(r0 + 8) * APITCH + c0    ]);
                af[mt][2] = __float_as_uint(As[(r0    ) * APITCH + c0 + 4]);
                af[mt][3] = __float_as_uint(As[(r0 + 8) * APITCH + c0 + 4]);
            }
            uint32_t bf[4][2];
#pragma unroll
            for (int nt = 0; nt < 4; ++nt) {
                const int cn = wn * 32 + nt * 8 + g;
                bf[nt][0] = __float_as_uint(Bs[(ks * 8 + tig    ) * BPITCH + cn]);
                bf[nt][1] = __float_as_uint(Bs[(ks * 8 + tig + 4) * BPITCH + cn]);
            }
#pragma unroll
            for (int mt = 0; mt < 4; ++mt)
#pragma unroll
                for (int nt = 0; nt < 4; ++nt)
                    mma_tf32(acc[mt][nt], af[mt], bf[nt]);
        }
        __syncthreads();
    }

#pragma unroll
    for (int mt = 0; mt < 4; ++mt) {
        const int row = m0 + wm * 64 + mt * 16 + g;
#pragma unroll
        for (int nt = 0; nt < 4; ++nt) {
            const int col = n0 + wn * 32 + nt * 8 + tig * 2;
            float b0 = 0.f, b1 = 0.f;
            if (bias) { b0 = bias[col]; b1 = bias[col + 1]; }
            float2 v0, v1;
            v0.x = acc[mt][nt][0] + b0; v0.y = acc[mt][nt][1] + b1;
            v1.x = acc[mt][nt][2] + b0; v1.y = acc[mt][nt][3] + b1;
            *(float2*)&C[(size_t)row * N + col]       = v0;
            *(float2*)&C[(size_t)(row + 8) * N + col] = v1;
        }
    }
}

// ===========================================================================
// position dtype detection
// ===========================================================================
__global__ void detect_pos_kernel(const int* __restrict__ p32) {
    if (threadIdx.x == 0 && blockIdx.x == 0)
        g_posflag = (p32[1] == 1 && p32[2] == 2) ? 1 : 0;
}

// ===========================================================================
// RoPE (GPT-J interleaved), in-place on q heads 0..31 and k heads 32..33
// ===========================================================================
__global__ void rope_kernel(const void* __restrict__ posraw) {
    const int total = MTOK * (NH_ + NKV_) * (ROT_ / 2);
    int idx = blockIdx.x * blockDim.x + threadIdx.x;
    if (idx >= total) return;

    const int i    = idx & 31;
    const int head = (idx >> 5) % (NH_ + NKV_);
    const int t    = idx / (32 * (NH_ + NKV_));

    long long pos;
    if (g_posflag) pos = ((const int*)posraw)[t];
    else           pos = ((const long long*)posraw)[t];

    const double e  = (double)(2 * i) / 64.0;
    const float inv = (float)(1.0 / pow(10000.0, e));
    const float fr  = (float)pos * inv;
    float sn, cs;
    sincosf(fr, &sn, &cs);

    size_t col;
    if (head < NH_) col = (size_t)head * HD_ + 2 * i;
    else            col = (size_t)NH_ * HD_ + (size_t)(head - NH_) * HD_ + 2 * i;

    float* p = g_qkv + (size_t)t * QKV_ + col;
    const float x1 = p[0];
    const float x2 = p[1];
    p[0] = x1 * cs - x2 * sn;
    p[1] = x2 * cs + x1 * sn;
}

// ===========================================================================
// Tensor-core flash attention, causal, GQA.
// BQ=128 per CTA, 8 m-warps (16 q-rows each, softmax warp-local), BK=32.
// QK^T: 3-term split tf32 (Qh*Kh + Ql*Kh + Qh*Kl)  -> ~fp32 accuracy.
// PV:   2-term (Ph*V + Pl*V), V tf32-rounded.
// K/V double-buffered with register prefetch. ctx written tf32-rounded.
// ===========================================================================
#define ATTN_SMEM_FLOATS (128*132 + 2*32*132 + 2*32*132 + 2*128*36 + 128*36 + 128*36)
#define ATTN_SMEM (ATTN_SMEM_FLOATS * 4)   // 208896 B

__global__ void __launch_bounds__(256) attn_kernel() {
    extern __shared__ float sm[];
    float* Qs  = sm;                        // [128][132] fp32 (pre-scaled)
    float* KhB = Qs  + 128 * 132;           // [2][32][132] tf32 hi
    float* KlB = KhB + 2 * 32 * 132;        // [2][32][132] tf32 lo
    float* VtB = KlB + 2 * 32 * 132;        // [2][128][36] V^T tf32
    float* Ph  = VtB + 2 * 128 * 36;        // [128][36] P hi
    float* Pl  = Ph  + 128 * 36;            // [128][36] P lo

    const int tid  = threadIdx.x;
    const int wid  = tid >> 5;
    const int lane = tid & 31;
    const int g    = lane >> 2;
    const int tig  = lane & 3;
    const int wrow = wid * 16;

    const int qt = blockIdx.x;
    const int bh = blockIdx.y;
    const int b  = bh >> 5;
    const int h  = bh & 31;
    const int kh = h >> 4;
    const int q0 = qt * 128;
    const float scale = 0.08838834764831845f;

    // ---- Q fill (scaled, fp32) ----
#pragma unroll
    for (int it = 0; it < 16; ++it) {
        const int id = tid + it * 256;
        const int r  = id >> 5;
        const int c4 = (id & 31) << 2;
        float4 v = *(const float4*)(g_qkv +
            (size_t)(b * S_ + q0 + r) * QKV_ + (size_t)h * HD_ + c4);
        v.x *= scale; v.y *= scale; v.z *= scale; v.w *= scale;
        *(float4*)&Qs[r * 132 + c4] = v;
    }

    float m_iA = -INFINITY, m_iB = -INFINITY, l_iA = 0.f, l_iB = 0.f;
    float O[16][4];
#pragma unroll
    for (int nf = 0; nf < 16; ++nf) {
        O[nf][0] = 0.f; O[nf][1] = 0.f; O[nf][2] = 0.f; O[nf][3] = 0.f;
    }

    const int NT = 4 * qt + 4;
    float4 kreg[4], vreg[4];

    // prefetch tile 0
#pragma unroll
    for (int it = 0; it < 4; ++it) {
        const int r = wid + 8 * it;
        kreg[it] = *(const float4*)(g_qkv + (size_t)(b * S_ + r) * QKV_ +
                                    (size_t)(NH_ + kh) * HD_ + lane * 4);
        vreg[it] = *(const float4*)(g_qkv + (size_t)(b * S_ + lane) * QKV_ +
                                    (size_t)(NH_ + NKV_ + kh) * HD_ + (wid + 8 * it) * 4);
    }

    for (int kt = 0; kt < NT; ++kt) {
        const int s  = kt & 1;
        const int k0 = kt * 32;
        float* Kh = KhB + s * 32 * 132;
        float* Kl = KlB + s * 32 * 132;
        float* Vt = VtB + s * 128 * 36;

        // ---- store prefetched K (split hi/lo) and V^T (tf32) into stage s ----
#pragma unroll
        for (int it = 0; it < 4; ++it) {
            const int r = wid + 8 * it;
            const float4 k = kreg[it];
            float4 hi, lo;
            hi.x = rna_f(k.x); lo.x = rna_f(k.x - hi.x);
            hi.y = rna_f(k.y); lo.y = rna_f(k.y - hi.y);
            hi.z = rna_f(k.z); lo.z = rna_f(k.z - hi.z);
            hi.w = rna_f(k.w); lo.w = rna_f(k.w - hi.w);
            *(float4*)&Kh[r * 132 + lane * 4] = hi;
            *(float4*)&Kl[r * 132 + lane * 4] = lo;
            const float4 v = vreg[it];
            const int c4 = (wid + 8 * it) * 4;
            Vt[(c4 + 0) * 36 + lane] = rna_f(v.x);
            Vt[(c4 + 1) * 36 + lane] = rna_f(v.y);
            Vt[(c4 + 2) * 36 + lane] = rna_f(v.z);
            Vt[(c4 + 3) * 36 + lane] = rna_f(v.w);
        }
        __syncthreads();

        // prefetch next tile
        if (kt + 1 < NT) {
            const int k1 = (kt + 1) * 32;
#pragma unroll
            for (int it = 0; it < 4; ++it) {
                const int r = wid + 8 * it;
                kreg[it] = *(const float4*)(g_qkv + (size_t)(b * S_ + k1 + r) * QKV_ +
                                            (size_t)(NH_ + kh) * HD_ + lane * 4);
                vreg[it] = *(const float4*)(g_qkv + (size_t)(b * S_ + k1 + lane) * QKV_ +
                                            (size_t)(NH_ + NKV_ + kh) * HD_ + (wid + 8 * it) * 4);
            }
        }

        // ---- S = Q K^T  (3-term split tf32) ----
        float sacc[4][4];
#pragma unroll
        for (int nf = 0; nf < 4; ++nf) {
            sacc[nf][0] = 0.f; sacc[nf][1] = 0.f; sacc[nf][2] = 0.f; sacc[nf][3] = 0.f;
        }
#pragma unroll
        for (int ks = 0; ks < 16; ++ks) {
            const int c0 = ks * 8 + tig;
            const float ar0 = Qs[(wrow + g    ) * 132 + c0    ];
            const float ar1 = Qs[(wrow + g + 8) * 132 + c0    ];
            const float ar2 = Qs[(wrow + g    ) * 132 + c0 + 4];
            const float ar3 = Qs[(wrow + g + 8) * 132 + c0 + 4];
            uint32_t ah[4], al[4];
            ah[0] = cvt_rna(ar0); al[0] = cvt_rna(ar0 - __uint_as_float(ah[0]));
            ah[1] = cvt_rna(ar1); al[1] = cvt_rna(ar1 - __uint_as_float(ah[1]));
            ah[2] = cvt_rna(ar2); al[2] = cvt_rna(ar2 - __uint_as_float(ah[2]));
            ah[3] = cvt_rna(ar3); al[3] = cvt_rna(ar3 - __uint_as_float(ah[3]));
#pragma unroll
            for (int nf = 0; nf < 4; ++nf) {
                const int n = nf * 8 + g;
                uint32_t bh2[2], bl2[2];
                bh2[0] = __float_as_uint(Kh[n * 132 + c0    ]);
                bh2[1] = __float_as_uint(Kh[n * 132 + c0 + 4]);
                bl2[0] = __float_as_uint(Kl[n * 132 + c0    ]);
                bl2[1] = __float_as_uint(Kl[n * 132 + c0 + 4]);
                mma_tf32(sacc[nf], ah, bh2);
                mma_tf32(sacc[nf], al, bh2);
                mma_tf32(sacc[nf], ah, bl2);
            }
        }

        // ---- causal mask ----
        const int rowA = q0 + wrow + g;
        const int rowB = rowA + 8;
        if (k0 + 31 > rowA) {
#pragma unroll
            for (int nf = 0; nf < 4; ++nf) {
                const int col = k0 + nf * 8 + tig * 2;
                if (col     > rowA) sacc[nf][0] = -INFINITY;
                if (col + 1 > rowA) sacc[nf][1] = -INFINITY;
                if (col     > rowB) sacc[nf][2] = -INFINITY;
                if (col + 1 > rowB) sacc[nf][3] = -INFINITY;
            }
        }

        // ---- online softmax (fp32, warp-local rows) ----
        float mA = -INFINITY, mB = -INFINITY;
#pragma unroll
        for (int nf = 0; nf < 4; ++nf) {
            mA = fmaxf(mA, fmaxf(sacc[nf][0], sacc[nf][1]));
            mB = fmaxf(mB, fmaxf(sacc[nf][2], sacc[nf][3]));
        }
        mA = fmaxf(mA, __shfl_xor_sync(0xffffffffu, mA, 1));
        mA = fmaxf(mA, __shfl_xor_sync(0xffffffffu, mA, 2));
        mB = fmaxf(mB, __shfl_xor_sync(0xffffffffu, mB, 1));
        mB = fmaxf(mB, __shfl_xor_sync(0xffffffffu, mB, 2));

        const float mnA = fmaxf(m_iA, mA);
        const float mnB = fmaxf(m_iB, mB);
        const float aA  = __expf(m_iA - mnA);
        const float aB  = __expf(m_iB - mnB);
        m_iA = mnA; m_iB = mnB;

        float rsA = 0.f, rsB = 0.f;
#pragma unroll
        for (int nf = 0; nf < 4; ++nf) {
            const float p0 = __expf(sacc[nf][0] - mnA);
            const float p1 = __expf(sacc[nf][1] - mnA);
            const float p2 = __expf(sacc[nf][2] - mnB);
            const float p3 = __expf(sacc[nf][3] - mnB);
            rsA += p0 + p1; rsB += p2 + p3;
            const float h0 = rna_f(p0), h1 = rna_f(p1);
            const float h2 = rna_f(p2), h3 = rna_f(p3);
            const int cA = (wrow + g    ) * 36 + nf * 8 + tig * 2;
            const int cB = (wrow + g + 8) * 36 + nf * 8 + tig * 2;
            *(float2*)&Ph[cA] = make_float2(h0, h1);
            *(float2*)&Pl[cA] = make_float2(p0 - h0, p1 - h1);
            *(float2*)&Ph[cB] = make_float2(h2, h3);
            *(float2*)&Pl[cB] = make_float2(p2 - h2, p3 - h3);
        }
        rsA += __shfl_xor_sync(0xffffffffu, rsA, 1);
        rsA += __shfl_xor_sync(0xffffffffu, rsA, 2);
        rsB += __shfl_xor_sync(0xffffffffu, rsB, 1);
        rsB += __shfl_xor_sync(0xffffffffu, rsB, 2);
        l_iA = l_iA * aA + rsA;
        l_iB = l_iB * aB + rsB;
#pragma unroll
        for (int nf = 0; nf < 16; ++nf) {
            O[nf][0] *= aA; O[nf][1] *= aA;
            O[nf][2] *= aB; O[nf][3] *= aB;
        }
        __syncwarp();

        // ---- O += P V  (2-term: Ph*V + Pl*V) ----
#pragma unroll
        for (int ks = 0; ks < 4; ++ks) {
            const int c0 = ks * 8 + tig;
            uint32_t ah[4], al[4];
            ah[0] = __float_as_uint(Ph[(wrow + g    ) * 36 + c0    ]);
            ah[1] = __float_as_uint(Ph[(wrow + g + 8) * 36 + c0    ]);
            ah[2] = __float_as_uint(Ph[(wrow + g    ) * 36 + c0 + 4]);
            ah[3] = __float_as_uint(Ph[(wrow + g + 8) * 36 + c0 + 4]);
            al[0] = __float_as_uint(Pl[(wrow + g    ) * 36 + c0    ]);
            al[1] = __float_as_uint(Pl[(wrow + g + 8) * 36 + c0    ]);
            al[2] = __float_as_uint(Pl[(wrow + g    ) * 36 + c0 + 4]);
            al[3] = __float_as_uint(Pl[(wrow + g + 8) * 36 + c0 + 4]);
#pragma unroll
            for (int nf = 0; nf < 16; ++nf) {
                uint32_t bv[2];
                bv[0] = __float_as_uint(Vt[(nf * 8 + g) * 36 + c0    ]);
                bv[1] = __float_as_uint(Vt[(nf * 8 + g) * 36 + c0 + 4]);
                mma_tf32(O[nf], ah, bv);
                mma_tf32(O[nf], al, bv);
            }
        }
    }

    // ---- epilogue: normalize, tf32-round, store ctx [B,S,NH,HD] ----
    const float invA = 1.f / l_iA;
    const float invB = 1.f / l_iB;
    const size_t baseA = ((size_t)(b * S_ + q0 + wrow + g    ) * NH_ + h) * HD_;
    const size_t baseB = ((size_t)(b * S_ + q0 + wrow + g + 8) * NH_ + h) * HD_;
#pragma unroll
    for (int nf = 0; nf < 16; ++nf) {
        const int col = nf * 8 + tig * 2;
        *(float2*)&g_ctx[baseA + col] =
            make_float2(rna_f(O[nf][0] * invA), rna_f(O[nf][1] * invA));
        *(float2*)&g_ctx[baseB + col] =
            make_float2(rna_f(O[nf][2] * invB), rna_f(O[nf][3] * invB));
    }
}

// ===========================================================================
// Launch
// ===========================================================================
extern "C" void kernel_launch(void* const* d_in, const int* in_sizes, int n_in,
                              void* d_out, int out_size)
{
    const float* hs   = (const float*)d_in[0];
    const void*  pos  = d_in[1];
    const float* Wqkv = (const float*)d_in[2];
    const float* bqkv = (const float*)d_in[3];
    const float* Wo   = (const float*)d_in[4];
    float*       out  = (float*)d_out;

    float *qkv, *ctx, *hsr, *wqr, *wor;
    cudaGetSymbolAddress((void**)&qkv, g_qkv);
    cudaGetSymbolAddress((void**)&ctx, g_ctx);
    cudaGetSymbolAddress((void**)&hsr, g_hsr);
    cudaGetSymbolAddress((void**)&wqr, g_wqr);
    cudaGetSymbolAddress((void**)&wor, g_wor);

    cudaFuncSetAttribute(attn_kernel,
                         cudaFuncAttributeMaxDynamicSharedMemorySize, ATTN_SMEM);
    cudaFuncSetAttribute(gemm_tf32_kernel,
                         cudaFuncAttributeMaxDynamicSharedMemorySize, GEMM_DSMEM);

    // 0) pre-round operands to tf32 (mainloop then needs no CVT)
    {
        int n4 = MTOK * H_ / 4;
        round_copy_kernel<<<(n4 + 255) / 256, 256>>>(hs, hsr, n4);
        n4 = H_ * QKV_ / 4;
        round_copy_kernel<<<(n4 + 255) / 256, 256>>>(Wqkv, wqr, n4);
        n4 = H_ * H_ / 4;
        round_copy_kernel<<<(n4 + 255) / 256, 256>>>(Wo, wor, n4);
    }

    // 1) QKV projection (tf32 mma.sync, CVT-free)
    gemm_tf32_kernel<<<(MTOK / 128) * (QKV_ / 128), 256, GEMM_DSMEM>>>(
        hsr, wqr, bqkv, qkv, MTOK, QKV_, H_, MTOK / 128, QKV_ / 128, 8);

    // 2) position dtype detect + RoPE in-place
    detect_pos_kernel<<<1, 32>>>((const int*)pos);
    {
        const int total = MTOK * (NH_ + NKV_) * (ROT_ / 2);
        rope_kernel<<<(total + 255) / 256, 256>>>(pos);
    }

    // 3) tensor-core causal GQA flash attention -> g_ctx (tf32-rounded)
    attn_kernel<<<dim3(S_ / 128, B_ * NH_), 256, ATTN_SMEM>>>();

    // 4) output projection (tf32 mma.sync, CVT-free)
    gemm_tf32_kernel<<<(MTOK / 128) * (H_ / 128), 256, GEMM_DSMEM>>>(
        ctx, wor, nullptr, out, MTOK, H_, H_, MTOK / 128, H_ / 128, 8);
}

// round 10
// speedup vs baseline: 2.7637x; 1.1144x over previous
#include <cuda_runtime.h>
#include <math.h>
#include <stdint.h>

// Problem constants
#define B_    2
#define S_    2048
#define H_    4096
#define NH_   32
#define NKV_  2
#define HD_   128
#define ROT_  64
#define QKV_  ((NH_ + 2*NKV_) * HD_)   // 4608
#define MTOK  (B_ * S_)                // 4096

// Scratch (static device globals: no allocation allowed)
__device__ float g_qkv[(size_t)MTOK * QKV_];        // [4096,4608] fp32
__device__ float g_ctx[(size_t)MTOK * NH_ * HD_];   // [4096,4096] tf32-rounded
__device__ float g_hsr[(size_t)MTOK * H_];          // hs rounded to tf32
__device__ float g_wqr[(size_t)H_ * QKV_];          // Wqkv rounded
__device__ float g_wor[(size_t)H_ * H_];            // Wo rounded
__device__ int   g_posflag;

// ===========================================================================
// helpers
// ===========================================================================
#define CP_ASYNC16(dst_smem, src_gmem) \
    asm volatile("cp.async.cg.shared.global [%0], [%1], 16;" \
                 :: "r"(dst_smem), "l"(src_gmem) : "memory")
#define CP_COMMIT() asm volatile("cp.async.commit_group;" ::: "memory")
#define CP_WAIT(n)  asm volatile("cp.async.wait_group %0;" :: "n"(n) : "memory")

__device__ __forceinline__ uint32_t smem_to_u32(const void* p) {
    uint32_t a;
    asm("{ .reg .u64 t; cvta.to.shared.u64 t, %1; cvt.u32.u64 %0, t; }"
        : "=r"(a) : "l"(p));
    return a;
}
__device__ __forceinline__ uint32_t cvt_rna(float x) {
    uint32_t r;
    asm("cvt.rna.tf32.f32 %0, %1;" : "=r"(r) : "f"(x));
    return r;
}
__device__ __forceinline__ float rna_f(float x) {
    return __uint_as_float(cvt_rna(x));
}
__device__ __forceinline__ void mma_tf32(float* c, const uint32_t* a, const uint32_t* b) {
    asm volatile(
        "mma.sync.aligned.m16n8k8.row.col.f32.tf32.tf32.f32 "
        "{%0,%1,%2,%3}, {%4,%5,%6,%7}, {%8,%9}, {%0,%1,%2,%3};"
        : "+f"(c[0]), "+f"(c[1]), "+f"(c[2]), "+f"(c[3])
        : "r"(a[0]), "r"(a[1]), "r"(a[2]), "r"(a[3]), "r"(b[0]), "r"(b[1]));
}

// ===========================================================================
// pre-round pass: out[i] = tf32_rna(in[i])
// ===========================================================================
__global__ void round_copy_kernel(const float* __restrict__ in,
                                  float* __restrict__ out, int n4) {
    int i = blockIdx.x * blockDim.x + threadIdx.x;
    if (i >= n4) return;
    float4 v = ((const float4*)in)[i];
    v.x = rna_f(v.x); v.y = rna_f(v.y);
    v.z = rna_f(v.z); v.w = rna_f(v.w);
    ((float4*)out)[i] = v;
}

// ===========================================================================
// tf32 mma.sync GEMM: C[M,N] = A[M,K] @ B[K,N] (+ bias[N]), row-major fp32.
// A and B are PRE-ROUNDED to tf32 values -> no CVT in mainloop (raw bits).
// CTA tile 128x128, BK=32, 256 threads (8 warps 2x4), warp tile 64x32.
// ===========================================================================
#define APITCH 36
#define BPITCH 132
#define ASTAGE (128 * APITCH * 4)
#define BSTAGE (32 * BPITCH * 4)
#define STAGE_BYTES (ASTAGE + BSTAGE)
#define GEMM_DSMEM (2 * STAGE_BYTES)

__global__ void __launch_bounds__(256, 2) gemm_tf32_kernel(
    const float* __restrict__ A, const float* __restrict__ Bm,
    const float* __restrict__ bias, float* __restrict__ C,
    int M, int N, int K, int mTiles, int nTiles, int group)
{
    extern __shared__ float dsm[];

    const int tid  = threadIdx.x;
    const int wid  = tid >> 5;
    const int lane = tid & 31;
    const int g    = lane >> 2;
    const int tig  = lane & 3;
    const int wm   = wid & 1;
    const int wn   = wid >> 1;

    const int bid = blockIdx.x;
    const int tpg = group * nTiles;
    const int gi  = bid / tpg;
    const int rr  = bid % tpg;
    const int rem = mTiles - gi * group;
    const int gm  = rem < group ? rem : group;
    const int tm  = gi * group + rr % gm;
    const int tn  = rr / gm;
    const int m0  = tm * 128;
    const int n0  = tn * 128;

    const uint32_t base_u = smem_to_u32(dsm);

    auto load_stage = [&](int s, int kc) {
        const uint32_t sA = base_u + s * STAGE_BYTES;
        const uint32_t sB = sA + ASTAGE;
        const float* Ab = A + (size_t)m0 * K + kc * 32;
        const float* Bb = Bm + (size_t)(kc * 32) * N + n0;
#pragma unroll
        for (int i = 0; i < 4; ++i) {
            const int id  = tid + i * 256;
            const int row = id >> 3;
            const int gg  = id & 7;
            CP_ASYNC16(sA + row * (APITCH * 4) + gg * 16,
                       Ab + (size_t)row * K + gg * 4);
        }
#pragma unroll
        for (int i = 0; i < 4; ++i) {
            const int id  = tid + i * 256;
            const int row = id >> 5;
            const int gg  = id & 31;
            CP_ASYNC16(sB + row * (BPITCH * 4) + gg * 16,
                       Bb + (size_t)row * N + gg * 4);
        }
    };

    float acc[4][4][4];
#pragma unroll
    for (int mt = 0; mt < 4; ++mt)
#pragma unroll
        for (int nt = 0; nt < 4; ++nt)
#pragma unroll
            for (int r = 0; r < 4; ++r) acc[mt][nt][r] = 0.f;

    const int NK = K / 32;
    load_stage(0, 0);
    CP_COMMIT();

    for (int kc = 0; kc < NK; ++kc) {
        const int s = kc & 1;
        if (kc + 1 < NK) { load_stage(s ^ 1, kc + 1); CP_COMMIT(); }
        if (kc + 1 < NK) { CP_WAIT(1); } else { CP_WAIT(0); }
        __syncthreads();

        const float* As = dsm + (size_t)s * (STAGE_BYTES / 4);
        const float* Bs = As + ASTAGE / 4;

#pragma unroll
        for (int ks = 0; ks < 4; ++ks) {
            uint32_t af[4][4];
#pragma unroll
            for (int mt = 0; mt < 4; ++mt) {
                const int r0 = wm * 64 + mt * 16 + g;
                const int c0 = ks * 8 + tig;
                af[mt][0] = __float_as_uint(As[(r0    ) * APITCH + c0    ]);
                af[mt][1] = __float_as_uint(As[(r0 + 8) * APITCH + c0    ]);
                af[mt][2] = __float_as_uint(As[(r0    ) * APITCH + c0 + 4]);
                af[mt][3] = __float_as_uint(As[(r0 + 8) * APITCH + c0 + 4]);
            }
            uint32_t bf[4][2];
#pragma unroll
            for (int nt = 0; nt < 4; ++nt) {
                const int cn = wn * 32 + nt * 8 + g;
                bf[nt][0] = __float_as_uint(Bs[(ks * 8 + tig    ) * BPITCH + cn]);
                bf[nt][1] = __float_as_uint(Bs[(ks * 8 + tig + 4) * BPITCH + cn]);
            }
#pragma unroll
            for (int mt = 0; mt < 4; ++mt)
#pragma unroll
                for (int nt = 0; nt < 4; ++nt)
                    mma_tf32(acc[mt][nt], af[mt], bf[nt]);
        }
        __syncthreads();
    }

#pragma unroll
    for (int mt = 0; mt < 4; ++mt) {
        const int row = m0 + wm * 64 + mt * 16 + g;
#pragma unroll
        for (int nt = 0; nt < 4; ++nt) {
            const int col = n0 + wn * 32 + nt * 8 + tig * 2;
            float b0 = 0.f, b1 = 0.f;
            if (bias) { b0 = bias[col]; b1 = bias[col + 1]; }
            float2 v0, v1;
            v0.x = acc[mt][nt][0] + b0; v0.y = acc[mt][nt][1] + b1;
            v1.x = acc[mt][nt][2] + b0; v1.y = acc[mt][nt][3] + b1;
            *(float2*)&C[(size_t)row * N + col]       = v0;
            *(float2*)&C[(size_t)(row + 8) * N + col] = v1;
        }
    }
}

// ===========================================================================
// position dtype detection
// ===========================================================================
__global__ void detect_pos_kernel(const int* __restrict__ p32) {
    if (threadIdx.x == 0 && blockIdx.x == 0)
        g_posflag = (p32[1] == 1 && p32[2] == 2) ? 1 : 0;
}

// ===========================================================================
// RoPE (GPT-J interleaved), in-place on q heads 0..31 and k heads 32..33
// ===========================================================================
__global__ void rope_kernel(const void* __restrict__ posraw) {
    const int total = MTOK * (NH_ + NKV_) * (ROT_ / 2);
    int idx = blockIdx.x * blockDim.x + threadIdx.x;
    if (idx >= total) return;

    const int i    = idx & 31;
    const int head = (idx >> 5) % (NH_ + NKV_);
    const int t    = idx / (32 * (NH_ + NKV_));

    long long pos;
    if (g_posflag) pos = ((const int*)posraw)[t];
    else           pos = ((const long long*)posraw)[t];

    const double e  = (double)(2 * i) / 64.0;
    const float inv = (float)(1.0 / pow(10000.0, e));
    const float fr  = (float)pos * inv;
    float sn, cs;
    sincosf(fr, &sn, &cs);

    size_t col;
    if (head < NH_) col = (size_t)head * HD_ + 2 * i;
    else            col = (size_t)NH_ * HD_ + (size_t)(head - NH_) * HD_ + 2 * i;

    float* p = g_qkv + (size_t)t * QKV_ + col;
    const float x1 = p[0];
    const float x2 = p[1];
    p[0] = x1 * cs - x2 * sn;
    p[1] = x2 * cs + x1 * sn;
}

// ===========================================================================
// Tensor-core flash attention, causal, GQA.
// BQ=128 per CTA, 8 m-warps (16 q-rows each, softmax warp-local), BK=32.
// QK^T: 2-term split tf32 (Qh*Kh + Ql*Kh), Q hi/lo split HOISTED to smem.
// PV:   1-term (P rna-rounded, V tf32-rounded).
// K/V double-buffered with register prefetch. ctx written tf32-rounded.
// ===========================================================================
#define ATTN_SMEM_FLOATS (2*128*132 + 2*32*132 + 2*128*36 + 128*36)
#define ATTN_SMEM (ATTN_SMEM_FLOATS * 4)   // 224256 B

__global__ void __launch_bounds__(256) attn_kernel() {
    extern __shared__ float sm[];
    float* Qh  = sm;                        // [128][132] tf32 hi (pre-scaled)
    float* Ql  = Qh  + 128 * 132;           // [128][132] tf32 lo
    float* KhB = Ql  + 128 * 132;           // [2][32][132] K tf32
    float* VtB = KhB + 2 * 32 * 132;        // [2][128][36] V^T tf32
    float* Ph  = VtB + 2 * 128 * 36;        // [128][36] P tf32

    const int tid  = threadIdx.x;
    const int wid  = tid >> 5;
    const int lane = tid & 31;
    const int g    = lane >> 2;
    const int tig  = lane & 3;
    const int wrow = wid * 16;

    const int qt = blockIdx.x;
    const int bh = blockIdx.y;
    const int b  = bh >> 5;
    const int h  = bh & 31;
    const int kh = h >> 4;
    const int q0 = qt * 128;
    const float scale = 0.08838834764831845f;

    // ---- Q fill: scale then split hi/lo (once per CTA) ----
#pragma unroll
    for (int it = 0; it < 16; ++it) {
        const int id = tid + it * 256;
        const int r  = id >> 5;
        const int c4 = (id & 31) << 2;
        float4 v = *(const float4*)(g_qkv +
            (size_t)(b * S_ + q0 + r) * QKV_ + (size_t)h * HD_ + c4);
        v.x *= scale; v.y *= scale; v.z *= scale; v.w *= scale;
        float4 hi, lo;
        hi.x = rna_f(v.x); lo.x = rna_f(v.x - hi.x);
        hi.y = rna_f(v.y); lo.y = rna_f(v.y - hi.y);
        hi.z = rna_f(v.z); lo.z = rna_f(v.z - hi.z);
        hi.w = rna_f(v.w); lo.w = rna_f(v.w - hi.w);
        *(float4*)&Qh[r * 132 + c4] = hi;
        *(float4*)&Ql[r * 132 + c4] = lo;
    }

    float m_iA = -INFINITY, m_iB = -INFINITY, l_iA = 0.f, l_iB = 0.f;
    float O[16][4];
#pragma unroll
    for (int nf = 0; nf < 16; ++nf) {
        O[nf][0] = 0.f; O[nf][1] = 0.f; O[nf][2] = 0.f; O[nf][3] = 0.f;
    }

    const int NT = 4 * qt + 4;
    float4 kreg[4], vreg[4];

    // prefetch tile 0
#pragma unroll
    for (int it = 0; it < 4; ++it) {
        const int r = wid + 8 * it;
        kreg[it] = *(const float4*)(g_qkv + (size_t)(b * S_ + r) * QKV_ +
                                    (size_t)(NH_ + kh) * HD_ + lane * 4);
        vreg[it] = *(const float4*)(g_qkv + (size_t)(b * S_ + lane) * QKV_ +
                                    (size_t)(NH_ + NKV_ + kh) * HD_ + (wid + 8 * it) * 4);
    }

    for (int kt = 0; kt < NT; ++kt) {
        const int s  = kt & 1;
        const int k0 = kt * 32;
        float* Kh = KhB + s * 32 * 132;
        float* Vt = VtB + s * 128 * 36;

        // ---- store prefetched K (tf32) and V^T (tf32) into stage s ----
#pragma unroll
        for (int it = 0; it < 4; ++it) {
            const int r = wid + 8 * it;
            const float4 k = kreg[it];
            float4 hi;
            hi.x = rna_f(k.x); hi.y = rna_f(k.y);
            hi.z = rna_f(k.z); hi.w = rna_f(k.w);
            *(float4*)&Kh[r * 132 + lane * 4] = hi;
            const float4 v = vreg[it];
            const int c4 = (wid + 8 * it) * 4;
            Vt[(c4 + 0) * 36 + lane] = rna_f(v.x);
            Vt[(c4 + 1) * 36 + lane] = rna_f(v.y);
            Vt[(c4 + 2) * 36 + lane] = rna_f(v.z);
            Vt[(c4 + 3) * 36 + lane] = rna_f(v.w);
        }
        __syncthreads();

        // prefetch next tile
        if (kt + 1 < NT) {
            const int k1 = (kt + 1) * 32;
#pragma unroll
            for (int it = 0; it < 4; ++it) {
                const int r = wid + 8 * it;
                kreg[it] = *(const float4*)(g_qkv + (size_t)(b * S_ + k1 + r) * QKV_ +
                                            (size_t)(NH_ + kh) * HD_ + lane * 4);
                vreg[it] = *(const float4*)(g_qkv + (size_t)(b * S_ + k1 + lane) * QKV_ +
                                            (size_t)(NH_ + NKV_ + kh) * HD_ + (wid + 8 * it) * 4);
            }
        }

        // ---- S = Q K^T  (2-term: Qh*Kh + Ql*Kh) ----
        float sacc[4][4];
#pragma unroll
        for (int nf = 0; nf < 4; ++nf) {
            sacc[nf][0] = 0.f; sacc[nf][1] = 0.f; sacc[nf][2] = 0.f; sacc[nf][3] = 0.f;
        }
#pragma unroll
        for (int ks = 0; ks < 16; ++ks) {
            const int c0 = ks * 8 + tig;
            uint32_t ah[4], al[4];
            ah[0] = __float_as_uint(Qh[(wrow + g    ) * 132 + c0    ]);
            ah[1] = __float_as_uint(Qh[(wrow + g + 8) * 132 + c0    ]);
            ah[2] = __float_as_uint(Qh[(wrow + g    ) * 132 + c0 + 4]);
            ah[3] = __float_as_uint(Qh[(wrow + g + 8) * 132 + c0 + 4]);
            al[0] = __float_as_uint(Ql[(wrow + g    ) * 132 + c0    ]);
            al[1] = __float_as_uint(Ql[(wrow + g + 8) * 132 + c0    ]);
            al[2] = __float_as_uint(Ql[(wrow + g    ) * 132 + c0 + 4]);
            al[3] = __float_as_uint(Ql[(wrow + g + 8) * 132 + c0 + 4]);
#pragma unroll
            for (int nf = 0; nf < 4; ++nf) {
                const int n = nf * 8 + g;
                uint32_t bh2[2];
                bh2[0] = __float_as_uint(Kh[n * 132 + c0    ]);
                bh2[1] = __float_as_uint(Kh[n * 132 + c0 + 4]);
                mma_tf32(sacc[nf], ah, bh2);
                mma_tf32(sacc[nf], al, bh2);
            }
        }

        // ---- causal mask ----
        const int rowA = q0 + wrow + g;
        const int rowB = rowA + 8;
        if (k0 + 31 > rowA) {
#pragma unroll
            for (int nf = 0; nf < 4; ++nf) {
                const int col = k0 + nf * 8 + tig * 2;
                if (col     > rowA) sacc[nf][0] = -INFINITY;
                if (col + 1 > rowA) sacc[nf][1] = -INFINITY;
                if (col     > rowB) sacc[nf][2] = -INFINITY;
                if (col + 1 > rowB) sacc[nf][3] = -INFINITY;
            }
        }

        // ---- online softmax (fp32, warp-local rows) ----
        float mA = -INFINITY, mB = -INFINITY;
#pragma unroll
        for (int nf = 0; nf < 4; ++nf) {
            mA = fmaxf(mA, fmaxf(sacc[nf][0], sacc[nf][1]));
            mB = fmaxf(mB, fmaxf(sacc[nf][2], sacc[nf][3]));
        }
        mA = fmaxf(mA, __shfl_xor_sync(0xffffffffu, mA, 1));
        mA = fmaxf(mA, __shfl_xor_sync(0xffffffffu, mA, 2));
        mB = fmaxf(mB, __shfl_xor_sync(0xffffffffu, mB, 1));
        mB = fmaxf(mB, __shfl_xor_sync(0xffffffffu, mB, 2));

        const float mnA = fmaxf(m_iA, mA);
        const float mnB = fmaxf(m_iB, mB);
        const float aA  = __expf(m_iA - mnA);
        const float aB  = __expf(m_iB - mnB);
        m_iA = mnA; m_iB = mnB;

        float rsA = 0.f, rsB = 0.f;
#pragma unroll
        for (int nf = 0; nf < 4; ++nf) {
            const float p0 = __expf(sacc[nf][0] - mnA);
            const float p1 = __expf(sacc[nf][1] - mnA);
            const float p2 = __expf(sacc[nf][2] - mnB);
            const float p3 = __expf(sacc[nf][3] - mnB);
            rsA += p0 + p1; rsB += p2 + p3;
            const int cA = (wrow + g    ) * 36 + nf * 8 + tig * 2;
            const int cB = (wrow + g + 8) * 36 + nf * 8 + tig * 2;
            *(float2*)&Ph[cA] = make_float2(rna_f(p0), rna_f(p1));
            *(float2*)&Ph[cB] = make_float2(rna_f(p2), rna_f(p3));
        }
        rsA += __shfl_xor_sync(0xffffffffu, rsA, 1);
        rsA += __shfl_xor_sync(0xffffffffu, rsA, 2);
        rsB += __shfl_xor_sync(0xffffffffu, rsB, 1);
        rsB += __shfl_xor_sync(0xffffffffu, rsB, 2);
        l_iA = l_iA * aA + rsA;
        l_iB = l_iB * aB + rsB;
#pragma unroll
        for (int nf = 0; nf < 16; ++nf) {
            O[nf][0] *= aA; O[nf][1] *= aA;
            O[nf][2] *= aB; O[nf][3] *= aB;
        }
        __syncwarp();

        // ---- O += P V  (1-term) ----
#pragma unroll
        for (int ks = 0; ks < 4; ++ks) {
            const int c0 = ks * 8 + tig;
            uint32_t ah[4];
            ah[0] = __float_as_uint(Ph[(wrow + g    ) * 36 + c0    ]);
            ah[1] = __float_as_uint(Ph[(wrow + g + 8) * 36 + c0    ]);
            ah[2] = __float_as_uint(Ph[(wrow + g    ) * 36 + c0 + 4]);
            ah[3] = __float_as_uint(Ph[(wrow + g + 8) * 36 + c0 + 4]);
#pragma unroll
            for (int nf = 0; nf < 16; ++nf) {
                uint32_t bv[2];
                bv[0] = __float_as_uint(Vt[(nf * 8 + g) * 36 + c0    ]);
                bv[1] = __float_as_uint(Vt[(nf * 8 + g) * 36 + c0 + 4]);
                mma_tf32(O[nf], ah, bv);
            }
        }
    }

    // ---- epilogue: normalize, tf32-round, store ctx [B,S,NH,HD] ----
    const float invA = 1.f / l_iA;
    const float invB = 1.f / l_iB;
    const size_t baseA = ((size_t)(b * S_ + q0 + wrow + g    ) * NH_ + h) * HD_;
    const size_t baseB = ((size_t)(b * S_ + q0 + wrow + g + 8) * NH_ + h) * HD_;
#pragma unroll
    for (int nf = 0; nf < 16; ++nf) {
        const int col = nf * 8 + tig * 2;
        *(float2*)&g_ctx[baseA + col] =
            make_float2(rna_f(O[nf][0] * invA), rna_f(O[nf][1] * invA));
        *(float2*)&g_ctx[baseB + col] =
            make_float2(rna_f(O[nf][2] * invB), rna_f(O[nf][3] * invB));
    }
}

// ===========================================================================
// Launch
// ===========================================================================
extern "C" void kernel_launch(void* const* d_in, const int* in_sizes, int n_in,
                              void* d_out, int out_size)
{
    const float* hs   = (const float*)d_in[0];
    const void*  pos  = d_in[1];
    const float* Wqkv = (const float*)d_in[2];
    const float* bqkv = (const float*)d_in[3];
    const float* Wo   = (const float*)d_in[4];
    float*       out  = (float*)d_out;

    float *qkv, *ctx, *hsr, *wqr, *wor;
    cudaGetSymbolAddress((void**)&qkv, g_qkv);
    cudaGetSymbolAddress((void**)&ctx, g_ctx);
    cudaGetSymbolAddress((void**)&hsr, g_hsr);
    cudaGetSymbolAddress((void**)&wqr, g_wqr);
    cudaGetSymbolAddress((void**)&wor, g_wor);

    cudaFuncSetAttribute(attn_kernel,
                         cudaFuncAttributeMaxDynamicSharedMemorySize, ATTN_SMEM);
    cudaFuncSetAttribute(gemm_tf32_kernel,
                         cudaFuncAttributeMaxDynamicSharedMemorySize, GEMM_DSMEM);

    // 0) pre-round operands to tf32 (mainloop then needs no CVT)
    {
        int n4 = MTOK * H_ / 4;
        round_copy_kernel<<<(n4 + 255) / 256, 256>>>(hs, hsr, n4);
        n4 = H_ * QKV_ / 4;
        round_copy_kernel<<<(n4 + 255) / 256, 256>>>(Wqkv, wqr, n4);
        n4 = H_ * H_ / 4;
        round_copy_kernel<<<(n4 + 255) / 256, 256>>>(Wo, wor, n4);
    }

    // 1) QKV projection (tf32 mma.sync, CVT-free)
    gemm_tf32_kernel<<<(MTOK / 128) * (QKV_ / 128), 256, GEMM_DSMEM>>>(
        hsr, wqr, bqkv, qkv, MTOK, QKV_, H_, MTOK / 128, QKV_ / 128, 8);

    // 2) position dtype detect + RoPE in-place
    detect_pos_kernel<<<1, 32>>>((const int*)pos);
    {
        const int total = MTOK * (NH_ + NKV_) * (ROT_ / 2);
        rope_kernel<<<(total + 255) / 256, 256>>>(pos);
    }

    // 3) tensor-core causal GQA flash attention -> g_ctx (tf32-rounded)
    attn_kernel<<<dim3(S_ / 128, B_ * NH_), 256, ATTN_SMEM>>>();

    // 4) output projection (tf32 mma.sync, CVT-free)
    gemm_tf32_kernel<<<(MTOK / 128) * (H_ / 128), 256, GEMM_DSMEM>>>(
        ctx, wor, nullptr, out, MTOK, H_, H_, MTOK / 128, H_ / 128, 8);
}

// round 14
// speedup vs baseline: 2.9978x; 1.0847x over previous
#include <cuda_runtime.h>
#include <math.h>
#include <stdint.h>

// Problem constants
#define B_    2
#define S_    2048
#define H_    4096
#define NH_   32
#define NKV_  2
#define HD_   128
#define ROT_  64
#define QKV_  ((NH_ + 2*NKV_) * HD_)   // 4608
#define MTOK  (B_ * S_)                // 4096

// Scratch (static device globals: no allocation allowed)
__device__ float g_qkv[(size_t)MTOK * QKV_];        // [4096,4608] fp32
__device__ float g_ctx[(size_t)MTOK * NH_ * HD_];   // [4096,4096] tf32-rounded
__device__ float g_hsr[(size_t)MTOK * H_];          // hs rounded to tf32
__device__ float g_wqr[(size_t)H_ * QKV_];          // Wqkv rounded
__device__ float g_wor[(size_t)H_ * H_];            // Wo rounded
__device__ int   g_posflag;

// ===========================================================================
// helpers
// ===========================================================================
#define CP_ASYNC16(dst_smem, src_gmem) \
    asm volatile("cp.async.cg.shared.global [%0], [%1], 16;" \
                 :: "r"(dst_smem), "l"(src_gmem) : "memory")
#define CP_COMMIT() asm volatile("cp.async.commit_group;" ::: "memory")
#define CP_WAIT(n)  asm volatile("cp.async.wait_group %0;" :: "n"(n) : "memory")

__device__ __forceinline__ uint32_t smem_to_u32(const void* p) {
    uint32_t a;
    asm("{ .reg .u64 t; cvta.to.shared.u64 t, %1; cvt.u32.u64 %0, t; }"
        : "=r"(a) : "l"(p));
    return a;
}
__device__ __forceinline__ uint32_t cvt_rna(float x) {
    uint32_t r;
    asm("cvt.rna.tf32.f32 %0, %1;" : "=r"(r) : "f"(x));
    return r;
}
__device__ __forceinline__ float rna_f(float x) {
    return __uint_as_float(cvt_rna(x));
}
__device__ __forceinline__ void mma_tf32(float* c, const uint32_t* a, const uint32_t* b) {
    asm volatile(
        "mma.sync.aligned.m16n8k8.row.col.f32.tf32.tf32.f32 "
        "{%0,%1,%2,%3}, {%4,%5,%6,%7}, {%8,%9}, {%0,%1,%2,%3};"
        : "+f"(c[0]), "+f"(c[1]), "+f"(c[2]), "+f"(c[3])
        : "r"(a[0]), "r"(a[1]), "r"(a[2]), "r"(a[3]), "r"(b[0]), "r"(b[1]));
}

// ===========================================================================
// pre-round pass: out[i] = tf32_rna(in[i])
// ===========================================================================
__global__ void round_copy_kernel(const float* __restrict__ in,
                                  float* __restrict__ out, int n4) {
    int i = blockIdx.x * blockDim.x + threadIdx.x;
    if (i >= n4) return;
    float4 v = ((const float4*)in)[i];
    v.x = rna_f(v.x); v.y = rna_f(v.y);
    v.z = rna_f(v.z); v.w = rna_f(v.w);
    ((float4*)out)[i] = v;
}

// ===========================================================================
// tf32 mma.sync GEMM: C[M,N] = A[M,K] @ B[K,N] (+ bias[N]), row-major fp32.
// Pre-rounded operands (no CVT in mainloop). CTA 128x128, BK=32, 8 warps.
// A smem [128][36] (banks 4g+tig, conflict-free), B smem [32][136]
// (banks 8tig+g, conflict-free -- 132 had 2-way conflicts). 3-stage cp.async.
// ===========================================================================
#define APITCH 36
#define BPITCH 136
#define ASTAGE (128 * APITCH * 4)              // 18432 B
#define BSTAGE (32 * BPITCH * 4)               // 17408 B
#define STAGE_BYTES (ASTAGE + BSTAGE)          // 35840 B
#define GEMM_DSMEM (3 * STAGE_BYTES)           // 107520 B

__global__ void __launch_bounds__(256, 2) gemm_tf32_kernel(
    const float* __restrict__ A, const float* __restrict__ Bm,
    const float* __restrict__ bias, float* __restrict__ C,
    int M, int N, int K, int mTiles, int nTiles, int group)
{
    extern __shared__ float dsm[];

    const int tid  = threadIdx.x;
    const int wid  = tid >> 5;
    const int lane = tid & 31;
    const int g    = lane >> 2;
    const int tig  = lane & 3;
    const int wm   = wid & 1;
    const int wn   = wid >> 1;

    const int bid = blockIdx.x;
    const int tpg = group * nTiles;
    const int gi  = bid / tpg;
    const int rr  = bid % tpg;
    const int rem = mTiles - gi * group;
    const int gm  = rem < group ? rem : group;
    const int tm  = gi * group + rr % gm;
    const int tn  = rr / gm;
    const int m0  = tm * 128;
    const int n0  = tn * 128;

    const uint32_t base_u = smem_to_u32(dsm);

    auto load_stage = [&](int s, int kc) {
        const uint32_t sA = base_u + s * STAGE_BYTES;
        const uint32_t sB = sA + ASTAGE;
        const float* Ab = A + (size_t)m0 * K + kc * 32;
        const float* Bb = Bm + (size_t)(kc * 32) * N + n0;
#pragma unroll
        for (int i = 0; i < 4; ++i) {
            const int id  = tid + i * 256;
            const int row = id >> 3;
            const int gg  = id & 7;
            CP_ASYNC16(sA + row * (APITCH * 4) + gg * 16,
                       Ab + (size_t)row * K + gg * 4);
        }
#pragma unroll
        for (int i = 0; i < 4; ++i) {
            const int id  = tid + i * 256;
            const int row = id >> 5;
            const int gg  = id & 31;
            CP_ASYNC16(sB + row * (BPITCH * 4) + gg * 16,
                       Bb + (size_t)row * N + gg * 4);
        }
    };

    float acc[4][4][4];
#pragma unroll
    for (int mt = 0; mt < 4; ++mt)
#pragma unroll
        for (int nt = 0; nt < 4; ++nt)
#pragma unroll
            for (int r = 0; r < 4; ++r) acc[mt][nt][r] = 0.f;

    const int NK = K / 32;
    load_stage(0, 0); CP_COMMIT();
    load_stage(1, 1); CP_COMMIT();

    int s_next = 2;   // stage to fill next
    for (int kc = 0; kc < NK; ++kc) {
        __syncthreads();   // all warps done with stage being overwritten below
        if (kc + 2 < NK) {
            load_stage(s_next, kc + 2); CP_COMMIT();
            if (++s_next == 3) s_next = 0;
        }
        if (kc + 2 < NK)      { CP_WAIT(2); }
        else if (kc + 1 < NK) { CP_WAIT(1); }
        else                  { CP_WAIT(0); }
        __syncthreads();

        const int s = kc % 3;
        const float* As = dsm + (size_t)s * (STAGE_BYTES / 4);
        const float* Bs = As + ASTAGE / 4;

#pragma unroll
        for (int ks = 0; ks < 4; ++ks) {
            uint32_t af[4][4];
#pragma unroll
            for (int mt = 0; mt < 4; ++mt) {
                const int r0 = wm * 64 + mt * 16 + g;
                const int c0 = ks * 8 + tig;
                af[mt][0] = __float_as_uint(As[(r0    ) * APITCH + c0    ]);
                af[mt][1] = __float_as_uint(As[(r0 + 8) * APITCH + c0    ]);
                af[mt][2] = __float_as_uint(As[(r0    ) * APITCH + c0 + 4]);
                af[mt][3] = __float_as_uint(As[(r0 + 8) * APITCH + c0 + 4]);
            }
            uint32_t bf[4][2];
#pragma unroll
            for (int nt = 0; nt < 4; ++nt) {
                const int cn = wn * 32 + nt * 8 + g;
                bf[nt][0] = __float_as_uint(Bs[(ks * 8 + tig    ) * BPITCH + cn]);
                bf[nt][1] = __float_as_uint(Bs[(ks * 8 + tig + 4) * BPITCH + cn]);
            }
#pragma unroll
            for (int mt = 0; mt < 4; ++mt)
#pragma unroll
                for (int nt = 0; nt < 4; ++nt)
                    mma_tf32(acc[mt][nt], af[mt], bf[nt]);
        }
    }

#pragma unroll
    for (int mt = 0; mt < 4; ++mt) {
        const int row = m0 + wm * 64 + mt * 16 + g;
#pragma unroll
        for (int nt = 0; nt < 4; ++nt) {
            const int col = n0 + wn * 32 + nt * 8 + tig * 2;
            float b0 = 0.f, b1 = 0.f;
            if (bias) { b0 = bias[col]; b1 = bias[col + 1]; }
            float2 v0, v1;
            v0.x = acc[mt][nt][0] + b0; v0.y = acc[mt][nt][1] + b1;
            v1.x = acc[mt][nt][2] + b0; v1.y = acc[mt][nt][3] + b1;
            *(float2*)&C[(size_t)row * N + col]       = v0;
            *(float2*)&C[(size_t)(row + 8) * N + col] = v1;
        }
    }
}

// ===========================================================================
// position dtype detection
// ===========================================================================
__global__ void detect_pos_kernel(const int* __restrict__ p32) {
    if (threadIdx.x == 0 && blockIdx.x == 0)
        g_posflag = (p32[1] == 1 && p32[2] == 2) ? 1 : 0;
}

// ===========================================================================
// RoPE (GPT-J interleaved), in-place on q heads 0..31 and k heads 32..33
// ===========================================================================
__global__ void rope_kernel(const void* __restrict__ posraw) {
    const int total = MTOK * (NH_ + NKV_) * (ROT_ / 2);
    int idx = blockIdx.x * blockDim.x + threadIdx.x;
    if (idx >= total) return;

    const int i    = idx & 31;
    const int head = (idx >> 5) % (NH_ + NKV_);
    const int t    = idx / (32 * (NH_ + NKV_));

    long long pos;
    if (g_posflag) pos = ((const int*)posraw)[t];
    else           pos = ((const long long*)posraw)[t];

    const double e  = (double)(2 * i) / 64.0;
    const float inv = (float)(1.0 / pow(10000.0, e));
    const float fr  = (float)pos * inv;
    float sn, cs;
    sincosf(fr, &sn, &cs);

    size_t col;
    if (head < NH_) col = (size_t)head * HD_ + 2 * i;
    else            col = (size_t)NH_ * HD_ + (size_t)(head - NH_) * HD_ + 2 * i;

    float* p = g_qkv + (size_t)t * QKV_ + col;
    const float x1 = p[0];
    const float x2 = p[1];
    p[0] = x1 * cs - x2 * sn;
    p[1] = x2 * cs + x1 * sn;
}

// ===========================================================================
// Tensor-core flash attention, causal, GQA. BQ=128, 8 m-warps, BK=32.
// QK^T: 1-term tf32 (Q,K rna-rounded). PV: 1-term, P permuted from
// accumulator regs to A-fragment regs via shfl (no P smem). K/V
// single-buffered (K register-prefetched across compute). 100.5KB smem
// -> 2 CTAs/SM.
// ===========================================================================
#define ATTN_SMEM ((128*132 + 32*132 + 128*36) * 4)   // 102912 B

__global__ void __launch_bounds__(256, 2) attn_kernel() {
    extern __shared__ float sm[];
    float* Qh = sm;                 // [128][132] tf32 (pre-scaled)
    float* Ks = Qh + 128 * 132;     // [32][132]  K tile (seq rows, hd cols)
    float* Vt = Ks + 32 * 132;      // [128][36]  V^T tile (hd rows, seq cols)

    const int tid  = threadIdx.x;
    const int wid  = tid >> 5;
    const int lane = tid & 31;
    const int g    = lane >> 2;
    const int tig  = lane & 3;
    const int wrow = wid * 16;

    const int qt = blockIdx.x;
    const int bh = blockIdx.y;
    const int b  = bh >> 5;
    const int h  = bh & 31;
    const int kh = h >> 4;
    const int q0 = qt * 128;
    const float scale = 0.08838834764831845f;

    // ---- Q fill: scale + rna (1-term) ----
#pragma unroll
    for (int it = 0; it < 16; ++it) {
        const int id = tid + it * 256;
        const int r  = id >> 5;
        const int c4 = (id & 31) << 2;
        float4 v = *(const float4*)(g_qkv +
            (size_t)(b * S_ + q0 + r) * QKV_ + (size_t)h * HD_ + c4);
        v.x = rna_f(v.x * scale); v.y = rna_f(v.y * scale);
        v.z = rna_f(v.z * scale); v.w = rna_f(v.w * scale);
        *(float4*)&Qh[r * 132 + c4] = v;
    }

    float m_iA = -INFINITY, m_iB = -INFINITY, l_iA = 0.f, l_iB = 0.f;
    float O[16][4];
#pragma unroll
    for (int nf = 0; nf < 16; ++nf) {
        O[nf][0] = 0.f; O[nf][1] = 0.f; O[nf][2] = 0.f; O[nf][3] = 0.f;
    }

    const int NT = 4 * qt + 4;
    float4 kreg[4];

    // K prefetch tile 0
#pragma unroll
    for (int it = 0; it < 4; ++it) {
        const int r = wid + 8 * it;
        kreg[it] = *(const float4*)(g_qkv + (size_t)(b * S_ + r) * QKV_ +
                                    (size_t)(NH_ + kh) * HD_ + lane * 4);
    }

    for (int kt = 0; kt < NT; ++kt) {
        const int k0 = kt * 32;

        // V for this tile (regs live only across the store)
        float4 vreg[4];
#pragma unroll
        for (int it = 0; it < 4; ++it)
            vreg[it] = *(const float4*)(g_qkv + (size_t)(b * S_ + k0 + lane) * QKV_ +
                                        (size_t)(NH_ + NKV_ + kh) * HD_ + (wid + 8 * it) * 4);

        __syncthreads();   // all warps done reading previous tile (and Q visible, kt=0)

#pragma unroll
        for (int it = 0; it < 4; ++it) {
            const int r = wid + 8 * it;
            float4 k = kreg[it];
            k.x = rna_f(k.x); k.y = rna_f(k.y);
            k.z = rna_f(k.z); k.w = rna_f(k.w);
            *(float4*)&Ks[r * 132 + lane * 4] = k;
            const float4 v = vreg[it];
            const int c4 = (wid + 8 * it) * 4;
            Vt[(c4 + 0) * 36 + lane] = rna_f(v.x);
            Vt[(c4 + 1) * 36 + lane] = rna_f(v.y);
            Vt[(c4 + 2) * 36 + lane] = rna_f(v.z);
            Vt[(c4 + 3) * 36 + lane] = rna_f(v.w);
        }
        __syncthreads();

        // K prefetch for next tile (regs, overlaps with compute below)
        if (kt + 1 < NT) {
            const int k1 = (kt + 1) * 32;
#pragma unroll
            for (int it = 0; it < 4; ++it) {
                const int r = wid + 8 * it;
                kreg[it] = *(const float4*)(g_qkv + (size_t)(b * S_ + k1 + r) * QKV_ +
                                            (size_t)(NH_ + kh) * HD_ + lane * 4);
            }
        }

        // ---- S = Q K^T (1-term tf32) ----
        float sacc[4][4];
#pragma unroll
        for (int nf = 0; nf < 4; ++nf) {
            sacc[nf][0] = 0.f; sacc[nf][1] = 0.f; sacc[nf][2] = 0.f; sacc[nf][3] = 0.f;
        }
#pragma unroll
        for (int ks = 0; ks < 16; ++ks) {
            const int c0 = ks * 8 + tig;
            uint32_t ah[4];
            ah[0] = __float_as_uint(Qh[(wrow + g    ) * 132 + c0    ]);
            ah[1] = __float_as_uint(Qh[(wrow + g + 8) * 132 + c0    ]);
            ah[2] = __float_as_uint(Qh[(wrow + g    ) * 132 + c0 + 4]);
            ah[3] = __float_as_uint(Qh[(wrow + g + 8) * 132 + c0 + 4]);
#pragma unroll
            for (int nf = 0; nf < 4; ++nf) {
                const int n = nf * 8 + g;
                uint32_t bk[2];
                bk[0] = __float_as_uint(Ks[n * 132 + c0    ]);
                bk[1] = __float_as_uint(Ks[n * 132 + c0 + 4]);
                mma_tf32(sacc[nf], ah, bk);
            }
        }

        // ---- causal mask ----
        const int rowA = q0 + wrow + g;
        const int rowB = rowA + 8;
        if (k0 + 31 > rowA) {
#pragma unroll
            for (int nf = 0; nf < 4; ++nf) {
                const int col = k0 + nf * 8 + tig * 2;
                if (col     > rowA) sacc[nf][0] = -INFINITY;
                if (col + 1 > rowA) sacc[nf][1] = -INFINITY;
                if (col     > rowB) sacc[nf][2] = -INFINITY;
                if (col + 1 > rowB) sacc[nf][3] = -INFINITY;
            }
        }

        // ---- online softmax (fp32, warp-local rows) ----
        float mA = -INFINITY, mB = -INFINITY;
#pragma unroll
        for (int nf = 0; nf < 4; ++nf) {
            mA = fmaxf(mA, fmaxf(sacc[nf][0], sacc[nf][1]));
            mB = fmaxf(mB, fmaxf(sacc[nf][2], sacc[nf][3]));
        }
        mA = fmaxf(mA, __shfl_xor_sync(0xffffffffu, mA, 1));
        mA = fmaxf(mA, __shfl_xor_sync(0xffffffffu, mA, 2));
        mB = fmaxf(mB, __shfl_xor_sync(0xffffffffu, mB, 1));
        mB = fmaxf(mB, __shfl_xor_sync(0xffffffffu, mB, 2));

        const float mnA = fmaxf(m_iA, mA);
        const float mnB = fmaxf(m_iB, mB);
        const float aA  = __expf(m_iA - mnA);
        const float aB  = __expf(m_iB - mnB);
        m_iA = mnA; m_iB = mnB;

        // P in accumulator-layout regs, rna-rounded
        uint32_t Pr[4][4];
        float rsA = 0.f, rsB = 0.f;
#pragma unroll
        for (int nf = 0; nf < 4; ++nf) {
            const float p0 = __expf(sacc[nf][0] - mnA);
            const float p1 = __expf(sacc[nf][1] - mnA);
            const float p2 = __expf(sacc[nf][2] - mnB);
            const float p3 = __expf(sacc[nf][3] - mnB);
            rsA += p0 + p1; rsB += p2 + p3;
            Pr[nf][0] = cvt_rna(p0); Pr[nf][1] = cvt_rna(p1);
            Pr[nf][2] = cvt_rna(p2); Pr[nf][3] = cvt_rna(p3);
        }
        rsA += __shfl_xor_sync(0xffffffffu, rsA, 1);
        rsA += __shfl_xor_sync(0xffffffffu, rsA, 2);
        rsB += __shfl_xor_sync(0xffffffffu, rsB, 1);
        rsB += __shfl_xor_sync(0xffffffffu, rsB, 2);
        l_iA = l_iA * aA + rsA;
        l_iB = l_iB * aB + rsB;
#pragma unroll
        for (int nf = 0; nf < 16; ++nf) {
            O[nf][0] *= aA; O[nf][1] *= aA;
            O[nf][2] *= aB; O[nf][3] *= aB;
        }

        // ---- O += P V: permute P acc-frag -> A-frag via shfl, then MMA ----
#pragma unroll
        for (int ks = 0; ks < 4; ++ks) {
            const int src1 = (lane & 28) | (tig >> 1);
            const int src2 = src1 + 2;
            const uint32_t u00 = __shfl_sync(0xffffffffu, Pr[ks][0], src1);
            const uint32_t u01 = __shfl_sync(0xffffffffu, Pr[ks][1], src1);
            const uint32_t u10 = __shfl_sync(0xffffffffu, Pr[ks][2], src1);
            const uint32_t u11 = __shfl_sync(0xffffffffu, Pr[ks][3], src1);
            const uint32_t u20 = __shfl_sync(0xffffffffu, Pr[ks][0], src2);
            const uint32_t u21 = __shfl_sync(0xffffffffu, Pr[ks][1], src2);
            const uint32_t u30 = __shfl_sync(0xffffffffu, Pr[ks][2], src2);
            const uint32_t u31 = __shfl_sync(0xffffffffu, Pr[ks][3], src2);
            uint32_t ap[4];
            ap[0] = (tig & 1) ? u01 : u00;
            ap[1] = (tig & 1) ? u11 : u10;
            ap[2] = (tig & 1) ? u21 : u20;
            ap[3] = (tig & 1) ? u31 : u30;
            const int c0 = ks * 8 + tig;
#pragma unroll
            for (int nf = 0; nf < 16; ++nf) {
                uint32_t bv[2];
                bv[0] = __float_as_uint(Vt[(nf * 8 + g) * 36 + c0    ]);
                bv[1] = __float_as_uint(Vt[(nf * 8 + g) * 36 + c0 + 4]);
                mma_tf32(O[nf], ap, bv);
            }
        }
    }

    // ---- epilogue: normalize, tf32-round, store ctx [B,S,NH,HD] ----
    const float invA = 1.f / l_iA;
    const float invB = 1.f / l_iB;
    const size_t baseA = ((size_t)(b * S_ + q0 + wrow + g    ) * NH_ + h) * HD_;
    const size_t baseB = ((size_t)(b * S_ + q0 + wrow + g + 8) * NH_ + h) * HD_;
#pragma unroll
    for (int nf = 0; nf < 16; ++nf) {
        const int col = nf * 8 + tig * 2;
        *(float2*)&g_ctx[baseA + col] =
            make_float2(rna_f(O[nf][0] * invA), rna_f(O[nf][1] * invA));
        *(float2*)&g_ctx[baseB + col] =
            make_float2(rna_f(O[nf][2] * invB), rna_f(O[nf][3] * invB));
    }
}

// ===========================================================================
// Launch
// ===========================================================================
extern "C" void kernel_launch(void* const* d_in, const int* in_sizes, int n_in,
                              void* d_out, int out_size)
{
    const float* hs   = (const float*)d_in[0];
    const void*  pos  = d_in[1];
    const float* Wqkv = (const float*)d_in[2];
    const float* bqkv = (const float*)d_in[3];
    const float* Wo   = (const float*)d_in[4];
    float*       out  = (float*)d_out;

    float *qkv, *ctx, *hsr, *wqr, *wor;
    cudaGetSymbolAddress((void**)&qkv, g_qkv);
    cudaGetSymbolAddress((void**)&ctx, g_ctx);
    cudaGetSymbolAddress((void**)&hsr, g_hsr);
    cudaGetSymbolAddress((void**)&wqr, g_wqr);
    cudaGetSymbolAddress((void**)&wor, g_wor);

    cudaFuncSetAttribute(attn_kernel,
                         cudaFuncAttributeMaxDynamicSharedMemorySize, ATTN_SMEM);
    cudaFuncSetAttribute(gemm_tf32_kernel,
                         cudaFuncAttributeMaxDynamicSharedMemorySize, GEMM_DSMEM);

    // 0) pre-round operands to tf32 (mainloop then needs no CVT)
    {
        int n4 = MTOK * H_ / 4;
        round_copy_kernel<<<(n4 + 255) / 256, 256>>>(hs, hsr, n4);
        n4 = H_ * QKV_ / 4;
        round_copy_kernel<<<(n4 + 255) / 256, 256>>>(Wqkv, wqr, n4);
        n4 = H_ * H_ / 4;
        round_copy_kernel<<<(n4 + 255) / 256, 256>>>(Wo, wor, n4);
    }

    // 1) QKV projection (tf32 mma.sync, conflict-free B, 3-stage)
    gemm_tf32_kernel<<<(MTOK / 128) * (QKV_ / 128), 256, GEMM_DSMEM>>>(
        hsr, wqr, bqkv, qkv, MTOK, QKV_, H_, MTOK / 128, QKV_ / 128, 8);

    // 2) position dtype detect + RoPE in-place
    detect_pos_kernel<<<1, 32>>>((const int*)pos);
    {
        const int total = MTOK * (NH_ + NKV_) * (ROT_ / 2);
        rope_kernel<<<(total + 255) / 256, 256>>>(pos);
    }

    // 3) tensor-core causal GQA flash attention -> g_ctx (tf32-rounded)
    attn_kernel<<<dim3(S_ / 128, B_ * NH_), 256, ATTN_SMEM>>>();

    // 4) output projection (tf32 mma.sync, conflict-free B, 3-stage)
    gemm_tf32_kernel<<<(MTOK / 128) * (H_ / 128), 256, GEMM_DSMEM>>>(
        ctx, wor, nullptr, out, MTOK, H_, H_, MTOK / 128, H_ / 128, 8);
}

// round 15
// speedup vs baseline: 3.0667x; 1.0230x over previous
#include <cuda_runtime.h>
#include <math.h>
#include <stdint.h>

// Problem constants
#define B_    2
#define S_    2048
#define H_    4096
#define NH_   32
#define NKV_  2
#define HD_   128
#define ROT_  64
#define QKV_  ((NH_ + 2*NKV_) * HD_)   // 4608
#define MTOK  (B_ * S_)                // 4096

// Scratch (static device globals: no allocation allowed)
__device__ float g_qkv[(size_t)MTOK * QKV_];        // [4096,4608] fp32
__device__ float g_ctx[(size_t)MTOK * NH_ * HD_];   // [4096,4096] tf32-rounded
__device__ float g_hsr[(size_t)MTOK * H_];          // hs rounded to tf32
__device__ float g_wqr[(size_t)H_ * QKV_];          // Wqkv rounded
__device__ float g_wor[(size_t)H_ * H_];            // Wo rounded
// attention pre-packed operands
__device__ float g_qp[(size_t)MTOK * NH_ * HD_];    // Q scaled+rounded, hd-paired
__device__ float g_kp[(size_t)MTOK * NKV_ * HD_];   // K rounded, hd-paired
__device__ float g_vt[(size_t)B_ * NKV_ * HD_ * S_];// V rounded, [b][kv][hd][seq-paired]
__device__ int   g_posflag;

// ===========================================================================
// helpers
// ===========================================================================
#define CP_ASYNC16(dst_smem, src_gmem) \
    asm volatile("cp.async.cg.shared.global [%0], [%1], 16;" \
                 :: "r"(dst_smem), "l"(src_gmem) : "memory")
#define CP_COMMIT() asm volatile("cp.async.commit_group;" ::: "memory")
#define CP_WAIT(n)  asm volatile("cp.async.wait_group %0;" :: "n"(n) : "memory")

__device__ __forceinline__ uint32_t smem_to_u32(const void* p) {
    uint32_t a;
    asm("{ .reg .u64 t; cvta.to.shared.u64 t, %1; cvt.u32.u64 %0, t; }"
        : "=r"(a) : "l"(p));
    return a;
}
__device__ __forceinline__ uint32_t cvt_rna(float x) {
    uint32_t r;
    asm("cvt.rna.tf32.f32 %0, %1;" : "=r"(r) : "f"(x));
    return r;
}
__device__ __forceinline__ float rna_f(float x) {
    return __uint_as_float(cvt_rna(x));
}
__device__ __forceinline__ void mma_tf32(float* c, const uint32_t* a, const uint32_t* b) {
    asm volatile(
        "mma.sync.aligned.m16n8k8.row.col.f32.tf32.tf32.f32 "
        "{%0,%1,%2,%3}, {%4,%5,%6,%7}, {%8,%9}, {%0,%1,%2,%3};"
        : "+f"(c[0]), "+f"(c[1]), "+f"(c[2]), "+f"(c[3])
        : "r"(a[0]), "r"(a[1]), "r"(a[2]), "r"(a[3]), "r"(b[0]), "r"(b[1]));
}
// paired column position within 8-groups: j -> (j&3)*2 + (j>>2)
__device__ __forceinline__ int ppos(int c) {
    return ((c >> 3) << 3) + ((c & 3) * 2) + ((c >> 2) & 1);
}

// ===========================================================================
// pre-round pass: out[i] = tf32_rna(in[i])
// ===========================================================================
__global__ void round_copy_kernel(const float* __restrict__ in,
                                  float* __restrict__ out, int n4) {
    int i = blockIdx.x * blockDim.x + threadIdx.x;
    if (i >= n4) return;
    float4 v = ((const float4*)in)[i];
    v.x = rna_f(v.x); v.y = rna_f(v.y);
    v.z = rna_f(v.z); v.w = rna_f(v.w);
    ((float4*)out)[i] = v;
}

// ===========================================================================
// attention operand prep: after rope, build
//   g_qp [t][h][hd-paired]     = rna(Q * scale)
//   g_kp [t][kv][hd-paired]    = rna(K)
//   g_vt [b][kv][hd][seq-pair] = rna(V)
// ===========================================================================
__global__ void prep_attn_kernel() {
    const float scale = 0.08838834764831845f;
    const int total = MTOK * (NH_ + 2 * NKV_) * HD_;
    int idx = blockIdx.x * blockDim.x + threadIdx.x;
    if (idx >= total) return;
    const int d    = idx & (HD_ - 1);
    const int head = (idx >> 7) % (NH_ + 2 * NKV_);
    const int t    = idx / (HD_ * (NH_ + 2 * NKV_));
    const float x  = g_qkv[(size_t)t * QKV_ + head * HD_ + d];
    if (head < NH_) {
        g_qp[((size_t)t * NH_ + head) * HD_ + ppos(d)] = rna_f(x * scale);
    } else if (head < NH_ + NKV_) {
        const int kv = head - NH_;
        g_kp[((size_t)t * NKV_ + kv) * HD_ + ppos(d)] = rna_f(x);
    } else {
        const int kv = head - NH_ - NKV_;
        const int b  = t >> 11;           // / S_
        const int s  = t & (S_ - 1);
        const int sp = ((s >> 3) << 3) + ((s & 3) * 2) + ((s >> 2) & 1);
        g_vt[(((size_t)(b * NKV_ + kv)) * HD_ + d) * S_ + sp] = rna_f(x);
    }
}

// ===========================================================================
// tf32 mma.sync GEMM (unchanged from R14): CTA 128x128, BK=32, 3-stage.
// ===========================================================================
#define APITCH 36
#define BPITCH 136
#define ASTAGE (128 * APITCH * 4)
#define BSTAGE (32 * BPITCH * 4)
#define STAGE_BYTES (ASTAGE + BSTAGE)
#define GEMM_DSMEM (3 * STAGE_BYTES)

__global__ void __launch_bounds__(256, 2) gemm_tf32_kernel(
    const float* __restrict__ A, const float* __restrict__ Bm,
    const float* __restrict__ bias, float* __restrict__ C,
    int M, int N, int K, int mTiles, int nTiles, int group)
{
    extern __shared__ float dsm[];

    const int tid  = threadIdx.x;
    const int wid  = tid >> 5;
    const int lane = tid & 31;
    const int g    = lane >> 2;
    const int tig  = lane & 3;
    const int wm   = wid & 1;
    const int wn   = wid >> 1;

    const int bid = blockIdx.x;
    const int tpg = group * nTiles;
    const int gi  = bid / tpg;
    const int rr  = bid % tpg;
    const int rem = mTiles - gi * group;
    const int gm  = rem < group ? rem : group;
    const int tm  = gi * group + rr % gm;
    const int tn  = rr / gm;
    const int m0  = tm * 128;
    const int n0  = tn * 128;

    const uint32_t base_u = smem_to_u32(dsm);

    auto load_stage = [&](int s, int kc) {
        const uint32_t sA = base_u + s * STAGE_BYTES;
        const uint32_t sB = sA + ASTAGE;
        const float* Ab = A + (size_t)m0 * K + kc * 32;
        const float* Bb = Bm + (size_t)(kc * 32) * N + n0;
#pragma unroll
        for (int i = 0; i < 4; ++i) {
            const int id  = tid + i * 256;
            const int row = id >> 3;
            const int gg  = id & 7;
            CP_ASYNC16(sA + row * (APITCH * 4) + gg * 16,
                       Ab + (size_t)row * K + gg * 4);
        }
#pragma unroll
        for (int i = 0; i < 4; ++i) {
            const int id  = tid + i * 256;
            const int row = id >> 5;
            const int gg  = id & 31;
            CP_ASYNC16(sB + row * (BPITCH * 4) + gg * 16,
                       Bb + (size_t)row * N + gg * 4);
        }
    };

    float acc[4][4][4];
#pragma unroll
    for (int mt = 0; mt < 4; ++mt)
#pragma unroll
        for (int nt = 0; nt < 4; ++nt)
#pragma unroll
            for (int r = 0; r < 4; ++r) acc[mt][nt][r] = 0.f;

    const int NK = K / 32;
    load_stage(0, 0); CP_COMMIT();
    load_stage(1, 1); CP_COMMIT();

    int s_next = 2;
    for (int kc = 0; kc < NK; ++kc) {
        __syncthreads();
        if (kc + 2 < NK) {
            load_stage(s_next, kc + 2); CP_COMMIT();
            if (++s_next == 3) s_next = 0;
        }
        if (kc + 2 < NK)      { CP_WAIT(2); }
        else if (kc + 1 < NK) { CP_WAIT(1); }
        else                  { CP_WAIT(0); }
        __syncthreads();

        const int s = kc % 3;
        const float* As = dsm + (size_t)s * (STAGE_BYTES / 4);
        const float* Bs = As + ASTAGE / 4;

#pragma unroll
        for (int ks = 0; ks < 4; ++ks) {
            uint32_t af[4][4];
#pragma unroll
            for (int mt = 0; mt < 4; ++mt) {
                const int r0 = wm * 64 + mt * 16 + g;
                const int c0 = ks * 8 + tig;
                af[mt][0] = __float_as_uint(As[(r0    ) * APITCH + c0    ]);
                af[mt][1] = __float_as_uint(As[(r0 + 8) * APITCH + c0    ]);
                af[mt][2] = __float_as_uint(As[(r0    ) * APITCH + c0 + 4]);
                af[mt][3] = __float_as_uint(As[(r0 + 8) * APITCH + c0 + 4]);
            }
            uint32_t bf[4][2];
#pragma unroll
            for (int nt = 0; nt < 4; ++nt) {
                const int cn = wn * 32 + nt * 8 + g;
                bf[nt][0] = __float_as_uint(Bs[(ks * 8 + tig    ) * BPITCH + cn]);
                bf[nt][1] = __float_as_uint(Bs[(ks * 8 + tig + 4) * BPITCH + cn]);
            }
#pragma unroll
            for (int mt = 0; mt < 4; ++mt)
#pragma unroll
                for (int nt = 0; nt < 4; ++nt)
                    mma_tf32(acc[mt][nt], af[mt], bf[nt]);
        }
    }

#pragma unroll
    for (int mt = 0; mt < 4; ++mt) {
        const int row = m0 + wm * 64 + mt * 16 + g;
#pragma unroll
        for (int nt = 0; nt < 4; ++nt) {
            const int col = n0 + wn * 32 + nt * 8 + tig * 2;
            float b0 = 0.f, b1 = 0.f;
            if (bias) { b0 = bias[col]; b1 = bias[col + 1]; }
            float2 v0, v1;
            v0.x = acc[mt][nt][0] + b0; v0.y = acc[mt][nt][1] + b1;
            v1.x = acc[mt][nt][2] + b0; v1.y = acc[mt][nt][3] + b1;
            *(float2*)&C[(size_t)row * N + col]       = v0;
            *(float2*)&C[(size_t)(row + 8) * N + col] = v1;
        }
    }
}

// ===========================================================================
// position dtype detection
// ===========================================================================
__global__ void detect_pos_kernel(const int* __restrict__ p32) {
    if (threadIdx.x == 0 && blockIdx.x == 0)
        g_posflag = (p32[1] == 1 && p32[2] == 2) ? 1 : 0;
}

// ===========================================================================
// RoPE (GPT-J interleaved), in-place on q heads 0..31 and k heads 32..33
// ===========================================================================
__global__ void rope_kernel(const void* __restrict__ posraw) {
    const int total = MTOK * (NH_ + NKV_) * (ROT_ / 2);
    int idx = blockIdx.x * blockDim.x + threadIdx.x;
    if (idx >= total) return;

    const int i    = idx & 31;
    const int head = (idx >> 5) % (NH_ + NKV_);
    const int t    = idx / (32 * (NH_ + NKV_));

    long long pos;
    if (g_posflag) pos = ((const int*)posraw)[t];
    else           pos = ((const long long*)posraw)[t];

    const double e  = (double)(2 * i) / 64.0;
    const float inv = (float)(1.0 / pow(10000.0, e));
    const float fr  = (float)pos * inv;
    float sn, cs;
    sincosf(fr, &sn, &cs);

    size_t col;
    if (head < NH_) col = (size_t)head * HD_ + 2 * i;
    else            col = (size_t)NH_ * HD_ + (size_t)(head - NH_) * HD_ + 2 * i;

    float* p = g_qkv + (size_t)t * QKV_ + col;
    const float x1 = p[0];
    const float x2 = p[1];
    p[0] = x1 * cs - x2 * sn;
    p[1] = x2 * cs + x1 * sn;
}

// ===========================================================================
// Tensor-core flash attention, causal, GQA. BQ=128, 8 m-warps, BK=16.
// All operands pre-rounded & pre-packed in gmem (paired cols -> LDS.64).
// Q once + K/V double-buffered via cp.async, 1 barrier per tile.
// smem 109KB -> 2 CTAs/SM.
// ===========================================================================
#define QPIT 136
#define KPIT 136
#define VPIT 24
#define KSTG (16 * KPIT * 4)            // 8704 B
#define VSTG (128 * VPIT * 4)           // 12288 B
#define ATTN_SMEM (128*QPIT*4 + 2*(KSTG + VSTG))   // 69632+41984 = 111616 B

__global__ void __launch_bounds__(256, 2) attn_kernel() {
    extern __shared__ float sm[];
    float* Qs  = sm;                    // [128][136] paired cols
    float* Kst = Qs + 128 * QPIT;       // [2][16][136] paired cols
    float* Vst = Kst + 2 * 16 * KPIT;   // [2][128][24] paired seq cols

    const int tid  = threadIdx.x;
    const int wid  = tid >> 5;
    const int lane = tid & 31;
    const int g    = lane >> 2;
    const int tig  = lane & 3;
    const int wrow = wid * 16;

    const int qt = blockIdx.x;
    const int bh = blockIdx.y;
    const int b  = bh >> 5;
    const int h  = bh & 31;
    const int kh = h >> 4;
    const int q0 = qt * 128;

    const uint32_t qs_u = smem_to_u32(Qs);
    const uint32_t ks_u = smem_to_u32(Kst);
    const uint32_t vs_u = smem_to_u32(Vst);

    const float* Qg = g_qp + ((size_t)(b * S_ + q0) * NH_ + h) * HD_;
    const float* Kg = g_kp + (size_t)b * S_ * NKV_ * HD_ + (size_t)kh * HD_;
    const float* Vg = g_vt + (size_t)(b * NKV_ + kh) * HD_ * S_;

    const int NT = 8 * qt + 8;

    auto load_kv = [&](int kt, int s) {
        const float* Kb = Kg + (size_t)(kt * 16) * (NKV_ * HD_);
        const float* Vb = Vg + kt * 16;
        const uint32_t kd = ks_u + s * KSTG;
        const uint32_t vd = vs_u + s * VSTG;
#pragma unroll
        for (int i = 0; i < 2; ++i) {   // K: 16 rows x 32 chunks
            const int id  = tid + i * 256;
            const int row = id >> 5;
            const int ch  = id & 31;
            CP_ASYNC16(kd + row * (KPIT * 4) + ch * 16,
                       Kb + (size_t)row * (NKV_ * HD_) + ch * 4);
        }
#pragma unroll
        for (int i = 0; i < 2; ++i) {   // V: 128 rows x 4 chunks
            const int id  = tid + i * 256;
            const int row = id >> 2;
            const int ch  = id & 3;
            CP_ASYNC16(vd + row * (VPIT * 4) + ch * 16,
                       Vb + (size_t)row * S_ + ch * 4);
        }
    };

    // prologue: Q (whole tile) + K0/V0 as group 0
#pragma unroll
    for (int i = 0; i < 16; ++i) {      // Q: 128 rows x 32 chunks
        const int id  = tid + i * 256;
        const int row = id >> 5;
        const int ch  = id & 31;
        CP_ASYNC16(qs_u + row * (QPIT * 4) + ch * 16,
                   Qg + (size_t)row * (NH_ * HD_) + ch * 4);
    }
    load_kv(0, 0);
    CP_COMMIT();

    float m_iA = -INFINITY, m_iB = -INFINITY, l_iA = 0.f, l_iB = 0.f;
    float O[16][4];
#pragma unroll
    for (int nf = 0; nf < 16; ++nf) {
        O[nf][0] = 0.f; O[nf][1] = 0.f; O[nf][2] = 0.f; O[nf][3] = 0.f;
    }

    for (int kt = 0; kt < NT; ++kt) {
        const int s  = kt & 1;
        const int k0 = kt * 16;

        CP_WAIT(0);          // my chunks of group kt landed
        __syncthreads();     // all threads' chunks visible; prev compute done

        if (kt + 1 < NT) {   // issue next tile into the other stage
            load_kv(kt + 1, s ^ 1);
            CP_COMMIT();
        }

        const float* Kh = Kst + s * (KSTG / 4);
        const float* Vt = Vst + s * (VSTG / 4);

        // ---- S = Q K^T (1-term tf32, LDS.64 fragments) ----
        float sacc[2][4];
#pragma unroll
        for (int nf = 0; nf < 2; ++nf) {
            sacc[nf][0] = 0.f; sacc[nf][1] = 0.f; sacc[nf][2] = 0.f; sacc[nf][3] = 0.f;
        }
#pragma unroll
        for (int ks = 0; ks < 16; ++ks) {
            const int co = ks * 8 + tig * 2;
            const float2 qa = *(const float2*)&Qs[(wrow + g    ) * QPIT + co];
            const float2 qb = *(const float2*)&Qs[(wrow + g + 8) * QPIT + co];
            uint32_t ah[4];
            ah[0] = __float_as_uint(qa.x); ah[1] = __float_as_uint(qb.x);
            ah[2] = __float_as_uint(qa.y); ah[3] = __float_as_uint(qb.y);
#pragma unroll
            for (int nf = 0; nf < 2; ++nf) {
                const float2 kb = *(const float2*)&Kh[(nf * 8 + g) * KPIT + co];
                uint32_t bk[2];
                bk[0] = __float_as_uint(kb.x); bk[1] = __float_as_uint(kb.y);
                mma_tf32(sacc[nf], ah, bk);
            }
        }

        // ---- causal mask ----
        const int rowA = q0 + wrow + g;
        const int rowB = rowA + 8;
        if (k0 + 15 > rowA) {
#pragma unroll
            for (int nf = 0; nf < 2; ++nf) {
                const int col = k0 + nf * 8 + tig * 2;
                if (col     > rowA) sacc[nf][0] = -INFINITY;
                if (col + 1 > rowA) sacc[nf][1] = -INFINITY;
                if (col     > rowB) sacc[nf][2] = -INFINITY;
                if (col + 1 > rowB) sacc[nf][3] = -INFINITY;
            }
        }

        // ---- online softmax (fp32, warp-local rows) ----
        float mA = fmaxf(fmaxf(sacc[0][0], sacc[0][1]), fmaxf(sacc[1][0], sacc[1][1]));
        float mB = fmaxf(fmaxf(sacc[0][2], sacc[0][3]), fmaxf(sacc[1][2], sacc[1][3]));
        mA = fmaxf(mA, __shfl_xor_sync(0xffffffffu, mA, 1));
        mA = fmaxf(mA, __shfl_xor_sync(0xffffffffu, mA, 2));
        mB = fmaxf(mB, __shfl_xor_sync(0xffffffffu, mB, 1));
        mB = fmaxf(mB, __shfl_xor_sync(0xffffffffu, mB, 2));

        const float mnA = fmaxf(m_iA, mA);
        const float mnB = fmaxf(m_iB, mB);
        const float aA  = __expf(m_iA - mnA);
        const float aB  = __expf(m_iB - mnB);
        m_iA = mnA; m_iB = mnB;

        uint32_t Pr[2][4];
        float rsA = 0.f, rsB = 0.f;
#pragma unroll
        for (int nf = 0; nf < 2; ++nf) {
            const float p0 = __expf(sacc[nf][0] - mnA);
            const float p1 = __expf(sacc[nf][1] - mnA);
            const float p2 = __expf(sacc[nf][2] - mnB);
            const float p3 = __expf(sacc[nf][3] - mnB);
            rsA += p0 + p1; rsB += p2 + p3;
            Pr[nf][0] = cvt_rna(p0); Pr[nf][1] = cvt_rna(p1);
            Pr[nf][2] = cvt_rna(p2); Pr[nf][3] = cvt_rna(p3);
        }
        rsA += __shfl_xor_sync(0xffffffffu, rsA, 1);
        rsA += __shfl_xor_sync(0xffffffffu, rsA, 2);
        rsB += __shfl_xor_sync(0xffffffffu, rsB, 1);
        rsB += __shfl_xor_sync(0xffffffffu, rsB, 2);
        l_iA = l_iA * aA + rsA;
        l_iB = l_iB * aB + rsB;
#pragma unroll
        for (int nf = 0; nf < 16; ++nf) {
            O[nf][0] *= aA; O[nf][1] *= aA;
            O[nf][2] *= aB; O[nf][3] *= aB;
        }

        // ---- O += P V: shfl-permute P acc-frag -> A-frag, LDS.64 B ----
#pragma unroll
        for (int ks = 0; ks < 2; ++ks) {
            const int src1 = (lane & 28) | (tig >> 1);
            const int src2 = src1 + 2;
            const uint32_t u00 = __shfl_sync(0xffffffffu, Pr[ks][0], src1);
            const uint32_t u01 = __shfl_sync(0xffffffffu, Pr[ks][1], src1);
            const uint32_t u10 = __shfl_sync(0xffffffffu, Pr[ks][2], src1);
            const uint32_t u11 = __shfl_sync(0xffffffffu, Pr[ks][3], src1);
            const uint32_t u20 = __shfl_sync(0xffffffffu, Pr[ks][0], src2);
            const uint32_t u21 = __shfl_sync(0xffffffffu, Pr[ks][1], src2);
            const uint32_t u30 = __shfl_sync(0xffffffffu, Pr[ks][2], src2);
            const uint32_t u31 = __shfl_sync(0xffffffffu, Pr[ks][3], src2);
            uint32_t ap[4];
            ap[0] = (tig & 1) ? u01 : u00;
            ap[1] = (tig & 1) ? u11 : u10;
            ap[2] = (tig & 1) ? u21 : u20;
            ap[3] = (tig & 1) ? u31 : u30;
            const int co = ks * 8 + tig * 2;
#pragma unroll
            for (int nf = 0; nf < 16; ++nf) {
                const float2 vv = *(const float2*)&Vt[(nf * 8 + g) * VPIT + co];
                uint32_t bv[2];
                bv[0] = __float_as_uint(vv.x); bv[1] = __float_as_uint(vv.y);
                mma_tf32(O[nf], ap, bv);
            }
        }
    }

    // ---- epilogue: normalize, tf32-round, store ctx [B,S,NH,HD] ----
    const float invA = 1.f / l_iA;
    const float invB = 1.f / l_iB;
    const size_t baseA = ((size_t)(b * S_ + q0 + wrow + g    ) * NH_ + h) * HD_;
    const size_t baseB = ((size_t)(b * S_ + q0 + wrow + g + 8) * NH_ + h) * HD_;
#pragma unroll
    for (int nf = 0; nf < 16; ++nf) {
        const int col = nf * 8 + tig * 2;
        *(float2*)&g_ctx[baseA + col] =
            make_float2(rna_f(O[nf][0] * invA), rna_f(O[nf][1] * invA));
        *(float2*)&g_ctx[baseB + col] =
            make_float2(rna_f(O[nf][2] * invB), rna_f(O[nf][3] * invB));
    }
}

// ===========================================================================
// Launch
// ===========================================================================
extern "C" void kernel_launch(void* const* d_in, const int* in_sizes, int n_in,
                              void* d_out, int out_size)
{
    const float* hs   = (const float*)d_in[0];
    const void*  pos  = d_in[1];
    const float* Wqkv = (const float*)d_in[2];
    const float* bqkv = (const float*)d_in[3];
    const float* Wo   = (const float*)d_in[4];
    float*       out  = (float*)d_out;

    float *qkv, *ctx, *hsr, *wqr, *wor;
    cudaGetSymbolAddress((void**)&qkv, g_qkv);
    cudaGetSymbolAddress((void**)&ctx, g_ctx);
    cudaGetSymbolAddress((void**)&hsr, g_hsr);
    cudaGetSymbolAddress((void**)&wqr, g_wqr);
    cudaGetSymbolAddress((void**)&wor, g_wor);

    cudaFuncSetAttribute(attn_kernel,
                         cudaFuncAttributeMaxDynamicSharedMemorySize, ATTN_SMEM);
    cudaFuncSetAttribute(gemm_tf32_kernel,
                         cudaFuncAttributeMaxDynamicSharedMemorySize, GEMM_DSMEM);

    // 0) pre-round GEMM operands to tf32
    {
        int n4 = MTOK * H_ / 4;
        round_copy_kernel<<<(n4 + 255) / 256, 256>>>(hs, hsr, n4);
        n4 = H_ * QKV_ / 4;
        round_copy_kernel<<<(n4 + 255) / 256, 256>>>(Wqkv, wqr, n4);
        n4 = H_ * H_ / 4;
        round_copy_kernel<<<(n4 + 255) / 256, 256>>>(Wo, wor, n4);
    }

    // 1) QKV projection (tf32 mma.sync)
    gemm_tf32_kernel<<<(MTOK / 128) * (QKV_ / 128), 256, GEMM_DSMEM>>>(
        hsr, wqr, bqkv, qkv, MTOK, QKV_, H_, MTOK / 128, QKV_ / 128, 8);

    // 2) position dtype detect + RoPE in-place
    detect_pos_kernel<<<1, 32>>>((const int*)pos);
    {
        const int total = MTOK * (NH_ + NKV_) * (ROT_ / 2);
        rope_kernel<<<(total + 255) / 256, 256>>>(pos);
    }

    // 2b) pack attention operands (round/scale/pair/transpose)
    {
        const int total = MTOK * (NH_ + 2 * NKV_) * HD_;
        prep_attn_kernel<<<(total + 255) / 256, 256>>>();
    }

    // 3) tensor-core causal GQA flash attention -> g_ctx (tf32-rounded)
    attn_kernel<<<dim3(S_ / 128, B_ * NH_), 256, ATTN_SMEM>>>();

    // 4) output projection (tf32 mma.sync)
    gemm_tf32_kernel<<<(MTOK / 128) * (H_ / 128), 256, GEMM_DSMEM>>>(
        ctx, wor, nullptr, out, MTOK, H_, H_, MTOK / 128, H_ / 128, 8);
}